// round 6
// baseline (speedup 1.0000x reference)
#include <cuda_runtime.h>
#include <cstdint>

typedef unsigned long long ull;

// Problem constants
#define L_DIM   2048
#define N_B     2
#define E_DIM   1024
#define H_N     16
#define D_H     64
#define S_DIM   2048
#define K_SEL   1176              // int(2048 * sigmoid(0.3))
#define T_SEL   (S_DIM - K_SEL)   // 872: 0-based ascending rank of threshold
#define SCS     2052              // score row stride in smem floats (bank-skewed)

// Scratch (static device arrays are allowed; cudaMalloc is not)
__device__ float g_Qp[4096 * 1024];
__device__ float g_Kp[4096 * 1024];
__device__ float g_Vp[4096 * 1024];
__device__ float g_O [4096 * 1024];

// ---------------------------------------------------------------------------
// Helpers
// ---------------------------------------------------------------------------
__device__ __forceinline__ unsigned f2key(float f) {
    unsigned u = __float_as_uint(f);
    return (u & 0x80000000u) ? ~u : (u | 0x80000000u);
}
__device__ __forceinline__ float key2f(unsigned k) {
    unsigned u = (k & 0x80000000u) ? (k ^ 0x80000000u) : ~k;
    return __uint_as_float(u);
}
// Fast e^x for x <= 0 (poly exp2, ~1e-7 rel err). Avoids MUFU bottleneck.
__device__ __forceinline__ float fexp(float x) {
    float y = x * 1.4426950408889634f;
    y = fmaxf(y, -120.0f);
    float fl = floorf(y);
    float f  = y - fl;
    float p  =             1.53533619e-4f;
    p = fmaf(p, f, 1.33988744e-3f);
    p = fmaf(p, f, 9.61843736e-3f);
    p = fmaf(p, f, 5.55033247e-2f);
    p = fmaf(p, f, 2.40226479e-1f);
    p = fmaf(p, f, 6.93147203e-1f);
    p = fmaf(p, f, 1.0f);
    return p * __int_as_float(((int)fl + 127) << 23);
}

// --- packed f32x2 ops (Blackwell, sm_100+) ---
__device__ __forceinline__ ull pk2(float a, float b) {
    ull r;
    asm("mov.b64 %0, {%1, %2};" : "=l"(r) : "r"(__float_as_uint(a)), "r"(__float_as_uint(b)));
    return r;
}
__device__ __forceinline__ ull fma2(ull a, ull b, ull c) {
    ull d;
    asm("fma.rn.f32x2 %0, %1, %2, %3;" : "=l"(d) : "l"(a), "l"(b), "l"(c));
    return d;
}
__device__ __forceinline__ ull add2(ull a, ull b) {
    ull d;
    asm("add.rn.f32x2 %0, %1, %2;" : "=l"(d) : "l"(a), "l"(b));
    return d;
}
__device__ __forceinline__ float2 upk(ull v) {
    unsigned lo, hi;
    asm("mov.b64 {%0, %1}, %2;" : "=r"(lo), "=r"(hi) : "l"(v));
    return make_float2(__uint_as_float(lo), __uint_as_float(hi));
}

// ---------------------------------------------------------------------------
// GEMM body: C[4096,1024] = A[4096,1024] @ B^T + bias (nn.Linear semantics)
// BM=BN=128, BK=16, 256 threads, 8x8 micro-tile via 32 FFMA2, reg prefetch.
// ---------------------------------------------------------------------------
__device__ __forceinline__
void gemm_body(const float* __restrict__ A, const float* __restrict__ B,
               const float* __restrict__ bias, float* __restrict__ C,
               int bm, int bn)
{
    __shared__ float As[16 * 128];
    __shared__ float Bs[16 * 128];
    const int tid = threadIdx.x;
    const int ty = tid >> 4, tx = tid & 15;
    const int rr = tid >> 2, k4 = tid & 3;   // loader coords

    ull acc[8][4];
#pragma unroll
    for (int i = 0; i < 8; ++i)
#pragma unroll
        for (int j = 0; j < 4; ++j) acc[i][j] = 0ull;

    const float* Abase = A + (size_t)(bm * 128 + rr) * 1024 + k4 * 4;
    const float* Bbase = B + (size_t)(bn * 128 + rr) * 1024 + k4 * 4;

    float4 pa0 = *(const float4*)(Abase);
    float4 pa1 = *(const float4*)(Abase + (size_t)64 * 1024);
    float4 pb0 = *(const float4*)(Bbase);
    float4 pb1 = *(const float4*)(Bbase + (size_t)64 * 1024);

    for (int kt = 0; kt < 64; ++kt) {
        As[(k4 * 4 + 0) * 128 + rr] = pa0.x;
        As[(k4 * 4 + 1) * 128 + rr] = pa0.y;
        As[(k4 * 4 + 2) * 128 + rr] = pa0.z;
        As[(k4 * 4 + 3) * 128 + rr] = pa0.w;
        As[(k4 * 4 + 0) * 128 + rr + 64] = pa1.x;
        As[(k4 * 4 + 1) * 128 + rr + 64] = pa1.y;
        As[(k4 * 4 + 2) * 128 + rr + 64] = pa1.z;
        As[(k4 * 4 + 3) * 128 + rr + 64] = pa1.w;
        Bs[(k4 * 4 + 0) * 128 + rr] = pb0.x;
        Bs[(k4 * 4 + 1) * 128 + rr] = pb0.y;
        Bs[(k4 * 4 + 2) * 128 + rr] = pb0.z;
        Bs[(k4 * 4 + 3) * 128 + rr] = pb0.w;
        Bs[(k4 * 4 + 0) * 128 + rr + 64] = pb1.x;
        Bs[(k4 * 4 + 1) * 128 + rr + 64] = pb1.y;
        Bs[(k4 * 4 + 2) * 128 + rr + 64] = pb1.z;
        Bs[(k4 * 4 + 3) * 128 + rr + 64] = pb1.w;
        __syncthreads();

        if (kt < 63) {
            const int off = (kt + 1) * 16;
            pa0 = *(const float4*)(Abase + off);
            pa1 = *(const float4*)(Abase + (size_t)64 * 1024 + off);
            pb0 = *(const float4*)(Bbase + off);
            pb1 = *(const float4*)(Bbase + (size_t)64 * 1024 + off);
        }

#pragma unroll
        for (int k = 0; k < 16; ++k) {
            const float4 a0 = *(const float4*)(As + k * 128 + ty * 4);
            const float4 a1 = *(const float4*)(As + k * 128 + 64 + ty * 4);
            const ulonglong2 bpa = *(const ulonglong2*)(Bs + k * 128 + tx * 4);
            const ulonglong2 bpb = *(const ulonglong2*)(Bs + k * 128 + 64 + tx * 4);
            ull ad[8];
            ad[0] = pk2(a0.x, a0.x); ad[1] = pk2(a0.y, a0.y);
            ad[2] = pk2(a0.z, a0.z); ad[3] = pk2(a0.w, a0.w);
            ad[4] = pk2(a1.x, a1.x); ad[5] = pk2(a1.y, a1.y);
            ad[6] = pk2(a1.z, a1.z); ad[7] = pk2(a1.w, a1.w);
            const ull bp[4] = {bpa.x, bpa.y, bpb.x, bpb.y};
#pragma unroll
            for (int ii = 0; ii < 8; ++ii)
#pragma unroll
                for (int jj = 0; jj < 4; ++jj)
                    acc[ii][jj] = fma2(ad[ii], bp[jj], acc[ii][jj]);
        }
        __syncthreads();
    }
    // Epilogue with bias
#pragma unroll
    for (int jh = 0; jh < 2; ++jh) {
        const int col = bn * 128 + jh * 64 + tx * 4;
        const float4 bb = *(const float4*)(bias + col);
#pragma unroll
        for (int ii = 0; ii < 8; ++ii) {
            const int row = bm * 128 + ((ii < 4) ? (ty * 4 + ii) : (64 + ty * 4 + ii - 4));
            const float2 c01 = upk(acc[ii][jh * 2 + 0]);
            const float2 c23 = upk(acc[ii][jh * 2 + 1]);
            float4 o;
            o.x = c01.x + bb.x;
            o.y = c01.y + bb.y;
            o.z = c23.x + bb.z;
            o.w = c23.y + bb.w;
            *(float4*)(C + (size_t)row * 1024 + col) = o;
        }
    }
}

// Fused Q/K/V projections: blockIdx.z selects the operand set.
__global__ __launch_bounds__(256, 2)
void gemm_qkv_kernel(const float* __restrict__ q, const float* __restrict__ k,
                     const float* __restrict__ v,
                     const float* __restrict__ Wq, const float* __restrict__ bq,
                     const float* __restrict__ Wk, const float* __restrict__ bk,
                     const float* __restrict__ Wv, const float* __restrict__ bv,
                     float* __restrict__ Qp, float* __restrict__ Kp, float* __restrict__ Vp)
{
    const int which = blockIdx.z;
    const float* A    = (which == 0) ? q  : (which == 1) ? k  : v;
    const float* B    = (which == 0) ? Wq : (which == 1) ? Wk : Wv;
    const float* bias = (which == 0) ? bq : (which == 1) ? bk : bv;
    float*       C    = (which == 0) ? Qp : (which == 1) ? Kp : Vp;
    gemm_body(A, B, bias, C, blockIdx.y, blockIdx.x);
}

__global__ __launch_bounds__(256, 2)
void gemm_o_kernel(const float* __restrict__ A, const float* __restrict__ B,
                   const float* __restrict__ bias, float* __restrict__ C)
{
    gemm_body(A, B, bias, C, blockIdx.y, blockIdx.x);
}

// ---------------------------------------------------------------------------
// Fused sparse attention: one block per (n, h, 16-query tile), 512 threads.
// Scores 16 x 2048 live in SMEM. Per-row exact radix select of the K_SEL-th
// largest score -> threshold; masked softmax; P @ V. f32x2 packed FMA.
// ---------------------------------------------------------------------------
#define ATTN_SMEM_FLOATS (16 * SCS + 16384 + 4096 + 48)
#define ATTN_SMEM_BYTES  (ATTN_SMEM_FLOATS * 4)

__global__ __launch_bounds__(512, 1)
void attn_kernel()
{
    extern __shared__ float sm[];
    float*    sc  = sm;                       // [16][SCS] scores -> weights
    float*    kv  = sm + 16 * SCS;            // K e-major [64][256] / V s-major [256][64]
    float*    R   = kv + 16384;               // 16KB shared: qt2 / hist / stage
    unsigned* s_tkey = (unsigned*)(R + 4096); // [16]
    unsigned* s_umax = s_tkey + 16;           // [16]
    float*    s_sum  = (float*)(s_umax + 16); // [16]
    ull*      qt2   = (ull*)R;                // [64][8] q row-pairs, dup-scaled
    unsigned* hist  = (unsigned*)R;           // 16 warps x 256 bins
    ull*      stage = (ull*)R;                // 256 x 2 partial O

    const int tid = threadIdx.x;
    const int n = blockIdx.z, h = blockIdx.y;
    const int l0 = blockIdx.x * 16;

    // ---- Load Q, pre-scale by 1/sqrt(D)=0.125, pack row-pairs: qt2[e*8+rp] ----
    {
        const int e = tid >> 3, rp = tid & 7;
        const float q0 = g_Qp[(size_t)((l0 + 2 * rp)     * 2 + n) * 1024 + h * 64 + e] * 0.125f;
        const float q1 = g_Qp[(size_t)((l0 + 2 * rp + 1) * 2 + n) * 1024 + h * 64 + e] * 0.125f;
        qt2[e * 8 + rp] = pk2(q0, q1);
    }

    // ---- Phase 1: scores = Q K^T; 8 rows x 1 key per thread, f32x2 over rows ----
    {
        const int rg = tid >> 8;              // 0/1 -> rows rg*8 .. rg*8+7
        const int col = tid & 255;
        const ull* qp = qt2 + rg * 4;
        for (int s0 = 0; s0 < S_DIM; s0 += 256) {
            // load K chunk transposed: kv[e][s_local]
#pragma unroll
            for (int i = 0; i < 8; ++i) {
                const int idx = i * 512 + tid;
                const int sr = idx & 255, e4 = idx >> 8;     // e4: 0..15
                const float4 k = *(const float4*)(g_Kp + (size_t)((s0 + sr) * 2 + n) * 1024 + h * 64 + e4 * 4);
                kv[(e4 * 4 + 0) * 256 + sr] = k.x;
                kv[(e4 * 4 + 1) * 256 + sr] = k.y;
                kv[(e4 * 4 + 2) * 256 + sr] = k.z;
                kv[(e4 * 4 + 3) * 256 + sr] = k.w;
            }
            __syncthreads();
            ull a0 = 0, a1 = 0, a2 = 0, a3 = 0;
            const float* kp = kv + col;
#pragma unroll 8
            for (int e = 0; e < 64; ++e) {
                const float kk = kp[e * 256];
                const ull kd = pk2(kk, kk);
                const ulonglong2 qa = *(const ulonglong2*)(qp + e * 8);
                const ulonglong2 qb = *(const ulonglong2*)(qp + e * 8 + 2);
                a0 = fma2(qa.x, kd, a0);
                a1 = fma2(qa.y, kd, a1);
                a2 = fma2(qb.x, kd, a2);
                a3 = fma2(qb.y, kd, a3);
            }
            const int rbase = rg * 8;
            float* sp = sc + s0 + col;
            float2 t;
            t = upk(a0); sp[(rbase + 0) * SCS] = t.x; sp[(rbase + 1) * SCS] = t.y;
            t = upk(a1); sp[(rbase + 2) * SCS] = t.x; sp[(rbase + 3) * SCS] = t.y;
            t = upk(a2); sp[(rbase + 4) * SCS] = t.x; sp[(rbase + 5) * SCS] = t.y;
            t = upk(a3); sp[(rbase + 6) * SCS] = t.x; sp[(rbase + 7) * SCS] = t.y;
            __syncthreads();
        }
    }

    // ---- Phase 2: per-row exact radix select, one warp per row ----
    {
        const int wid = tid >> 5, lane = tid & 31;
        const int row = wid;
        unsigned* hw = hist + wid * 256;
        const float* srow = sc + row * SCS;
        // row max
        unsigned km = 0;
#pragma unroll 8
        for (int j = 0; j < 64; ++j) {
            const unsigned k = f2key(srow[lane + 32 * j]);
            km = (k > km) ? k : km;
        }
#pragma unroll
        for (int o = 16; o > 0; o >>= 1) {
            const unsigned v = __shfl_xor_sync(0xffffffffu, km, o);
            km = (v > km) ? v : km;
        }
        // MSB-first byte radix select for ascending rank T_SEL
        unsigned prefix = 0;
        unsigned T = T_SEL;
#pragma unroll
        for (int b = 3; b >= 0; --b) {
            for (int i = lane; i < 256; i += 32) hw[i] = 0;
            __syncwarp();
            const unsigned himask = (b == 3) ? 0u : (0xFFFFFFFFu << ((b + 1) * 8));
            for (int j = 0; j < 64; ++j) {
                const unsigned key = f2key(srow[lane + 32 * j]);
                const bool act = ((key & himask) == prefix);
                const unsigned bin = (key >> (b * 8)) & 255;
                // warp-aggregated atomics: one per distinct bin per 32 keys
                const unsigned tag = act ? bin : (0x100u + (unsigned)lane);
                const unsigned grp = __match_any_sync(0xffffffffu, tag);
                if (act && lane == (__ffs(grp) - 1))
                    atomicAdd(&hw[bin], (unsigned)__popc(grp));
            }
            __syncwarp();
            unsigned c[8], lsum = 0;
#pragma unroll
            for (int i = 0; i < 8; ++i) { c[i] = hw[lane * 8 + i]; lsum += c[i]; }
            unsigned inc = lsum;
#pragma unroll
            for (int o = 1; o < 32; o <<= 1) {
                const unsigned v = __shfl_up_sync(0xffffffffu, inc, o);
                if (lane >= o) inc += v;
            }
            const unsigned exl = inc - lsum;
            const bool own = (T >= exl) && (T < exl + lsum);
            const unsigned bal = __ballot_sync(0xffffffffu, own);
            const int src = __ffs(bal) - 1;
            unsigned bsel = 0, nT = 0;
            if (own) {
                unsigned cum = exl;
#pragma unroll
                for (int i = 0; i < 8; ++i) {
                    if (T < cum + c[i]) { bsel = (unsigned)(lane * 8 + i); nT = T - cum; break; }
                    cum += c[i];
                }
            }
            bsel = __shfl_sync(0xffffffffu, bsel, src);
            nT   = __shfl_sync(0xffffffffu, nT, src);
            prefix |= bsel << (b * 8);
            T = nT;
            __syncwarp();
        }
        if (lane == 0) { s_tkey[row] = prefix; s_umax[row] = km; }
    }
    __syncthreads();

    // ---- Phase 3: masked exp weights + row sums (one warp per row, no atomics) ----
    {
        const int row = tid >> 5, lane = tid & 31;
        const unsigned tk = s_tkey[row];
        const float m = key2f(s_umax[row]);
        float lsum = 0.0f;
        float* srow = sc + row * SCS;
#pragma unroll 4
        for (int j = 0; j < 64; ++j) {
            const float x = srow[j * 32 + lane];
            float w = 0.0f;
            if (f2key(x) >= tk) w = fexp(x - m);
            srow[j * 32 + lane] = w;
            lsum += w;
        }
#pragma unroll
        for (int o = 16; o > 0; o >>= 1)
            lsum += __shfl_xor_sync(0xffffffffu, lsum, o);
        if (lane == 0) s_sum[row] = lsum;
    }
    __syncthreads();

    // ---- Phase 4: O = W @ V; 1 row x 4 d per thread, f32x2 over d, 2-way s-split ----
    const int g = tid >> 8, pos = tid & 255;
    const int orow = pos >> 4, dq = pos & 15;
    ull oa0 = 0, oa1 = 0;  // d-pairs (dq*4, dq*4+1), (dq*4+2, dq*4+3)
    for (int s0 = 0; s0 < S_DIM; s0 += 256) {
#pragma unroll
        for (int i = 0; i < 8; ++i) {
            const int idx = i * 512 + tid;
            const int sr = idx >> 4, d4 = idx & 15;
            const float4 v = *(const float4*)(g_Vp + (size_t)((s0 + sr) * 2 + n) * 1024 + h * 64 + d4 * 4);
            *(float4*)(kv + sr * 64 + d4 * 4) = v;
        }
        __syncthreads();
        const float* wp = sc + orow * SCS + s0 + g * 128;
        const float* vp = kv + (g * 128) * 64 + dq * 4;
#pragma unroll 8
        for (int sl = 0; sl < 128; ++sl) {
            const float w = wp[sl];
            const ull wd = pk2(w, w);
            const ulonglong2 v2 = *(const ulonglong2*)(vp + sl * 64);
            oa0 = fma2(wd, v2.x, oa0);
            oa1 = fma2(wd, v2.y, oa1);
        }
        __syncthreads();
    }

    // ---- Phase 5: cross-group reduce, normalize, scatter (d-major output) ----
    if (g == 1) {
        stage[pos * 2]     = oa0;
        stage[pos * 2 + 1] = oa1;
    }
    __syncthreads();
    if (g == 0) {
        const float2 r0 = upk(add2(oa0, stage[pos * 2]));
        const float2 r1 = upk(add2(oa1, stage[pos * 2 + 1]));
        const float inv = 1.0f / s_sum[orow];
        float* o = g_O + (size_t)((l0 + orow) * 2 + n) * 1024 + h;   // + d*16
        o[(dq * 4 + 0) * 16] = r0.x * inv;
        o[(dq * 4 + 1) * 16] = r0.y * inv;
        o[(dq * 4 + 2) * 16] = r1.x * inv;
        o[(dq * 4 + 3) * 16] = r1.y * inv;
    }
}

// ---------------------------------------------------------------------------
// Launch
// ---------------------------------------------------------------------------
extern "C" void kernel_launch(void* const* d_in, const int* in_sizes, int n_in,
                              void* d_out, int out_size)
{
    (void)in_sizes; (void)n_in; (void)out_size;
    const float* query = (const float*)d_in[0];
    const float* key   = (const float*)d_in[1];
    const float* value = (const float*)d_in[2];
    const float* Wq = (const float*)d_in[3];
    const float* bq = (const float*)d_in[4];
    const float* Wk = (const float*)d_in[5];
    const float* bk = (const float*)d_in[6];
    const float* Wv = (const float*)d_in[7];
    const float* bv = (const float*)d_in[8];
    const float* Wo = (const float*)d_in[9];
    const float* bo = (const float*)d_in[10];

    float *Qp, *Kp, *Vp, *O;
    cudaGetSymbolAddress((void**)&Qp, g_Qp);
    cudaGetSymbolAddress((void**)&Kp, g_Kp);
    cudaGetSymbolAddress((void**)&Vp, g_Vp);
    cudaGetSymbolAddress((void**)&O,  g_O);

    cudaFuncSetAttribute(attn_kernel, cudaFuncAttributeMaxDynamicSharedMemorySize,
                         ATTN_SMEM_BYTES);

    gemm_qkv_kernel<<<dim3(8, 32, 3), 256>>>(query, key, value,
                                             Wq, bq, Wk, bk, Wv, bv,
                                             Qp, Kp, Vp);

    attn_kernel<<<dim3(L_DIM / 16, H_N, N_B), 512, ATTN_SMEM_BYTES>>>();

    gemm_o_kernel<<<dim3(8, 32, 1), 256>>>(O, Wo, bo, (float*)d_out);
}

// round 7
// speedup vs baseline: 1.2242x; 1.2242x over previous
#include <cuda_runtime.h>
#include <cstdint>

typedef unsigned long long ull;

// Problem constants
#define L_DIM   2048
#define N_B     2
#define E_DIM   1024
#define H_N     16
#define D_H     64
#define S_DIM   2048
#define K_SEL   1176              // int(2048 * sigmoid(0.3))
#define T_SEL   (S_DIM - K_SEL)   // 872: 0-based ascending rank of threshold
#define SCS     2052              // score row stride in smem floats (bank-skewed)

#define ROWS    8                 // query rows per block
#define CHUNK   128               // keys per smem chunk
#define KSTR    65                // K smem row stride (conflict-free scalar reads)

// Scratch (static device arrays are allowed; cudaMalloc is not)
__device__ float g_Qp[4096 * 1024];
__device__ float g_Kp[4096 * 1024];
__device__ float g_Vp[4096 * 1024];
__device__ float g_O [4096 * 1024];

// ---------------------------------------------------------------------------
// Helpers
// ---------------------------------------------------------------------------
__device__ __forceinline__ unsigned f2key(float f) {
    unsigned u = __float_as_uint(f);
    return (u & 0x80000000u) ? ~u : (u | 0x80000000u);
}
__device__ __forceinline__ float key2f(unsigned k) {
    unsigned u = (k & 0x80000000u) ? (k ^ 0x80000000u) : ~k;
    return __uint_as_float(u);
}
// Fast e^x for x <= 0 (poly exp2, ~1e-7 rel err). Avoids MUFU bottleneck.
__device__ __forceinline__ float fexp(float x) {
    float y = x * 1.4426950408889634f;
    y = fmaxf(y, -120.0f);
    float fl = floorf(y);
    float f  = y - fl;
    float p  =             1.53533619e-4f;
    p = fmaf(p, f, 1.33988744e-3f);
    p = fmaf(p, f, 9.61843736e-3f);
    p = fmaf(p, f, 5.55033247e-2f);
    p = fmaf(p, f, 2.40226479e-1f);
    p = fmaf(p, f, 6.93147203e-1f);
    p = fmaf(p, f, 1.0f);
    return p * __int_as_float(((int)fl + 127) << 23);
}

// --- packed f32x2 ops (Blackwell, sm_100+) ---
__device__ __forceinline__ ull pk2(float a, float b) {
    ull r;
    asm("mov.b64 %0, {%1, %2};" : "=l"(r) : "r"(__float_as_uint(a)), "r"(__float_as_uint(b)));
    return r;
}
__device__ __forceinline__ ull fma2(ull a, ull b, ull c) {
    ull d;
    asm("fma.rn.f32x2 %0, %1, %2, %3;" : "=l"(d) : "l"(a), "l"(b), "l"(c));
    return d;
}
__device__ __forceinline__ ull add2(ull a, ull b) {
    ull d;
    asm("add.rn.f32x2 %0, %1, %2;" : "=l"(d) : "l"(a), "l"(b));
    return d;
}
__device__ __forceinline__ float2 upk(ull v) {
    unsigned lo, hi;
    asm("mov.b64 {%0, %1}, %2;" : "=r"(lo), "=r"(hi) : "l"(v));
    return make_float2(__uint_as_float(lo), __uint_as_float(hi));
}

// ---------------------------------------------------------------------------
// GEMM body: C[4096,1024] = A[4096,1024] @ B^T + bias (nn.Linear semantics)
// BM=BN=128, BK=16, 256 threads, 8x8 micro-tile via 32 FFMA2, reg prefetch.
// ---------------------------------------------------------------------------
__device__ __forceinline__
void gemm_body(const float* __restrict__ A, const float* __restrict__ B,
               const float* __restrict__ bias, float* __restrict__ C,
               int bm, int bn)
{
    __shared__ float As[16 * 128];
    __shared__ float Bs[16 * 128];
    const int tid = threadIdx.x;
    const int ty = tid >> 4, tx = tid & 15;
    const int rr = tid >> 2, k4 = tid & 3;   // loader coords

    ull acc[8][4];
#pragma unroll
    for (int i = 0; i < 8; ++i)
#pragma unroll
        for (int j = 0; j < 4; ++j) acc[i][j] = 0ull;

    const float* Abase = A + (size_t)(bm * 128 + rr) * 1024 + k4 * 4;
    const float* Bbase = B + (size_t)(bn * 128 + rr) * 1024 + k4 * 4;

    float4 pa0 = *(const float4*)(Abase);
    float4 pa1 = *(const float4*)(Abase + (size_t)64 * 1024);
    float4 pb0 = *(const float4*)(Bbase);
    float4 pb1 = *(const float4*)(Bbase + (size_t)64 * 1024);

    for (int kt = 0; kt < 64; ++kt) {
        As[(k4 * 4 + 0) * 128 + rr] = pa0.x;
        As[(k4 * 4 + 1) * 128 + rr] = pa0.y;
        As[(k4 * 4 + 2) * 128 + rr] = pa0.z;
        As[(k4 * 4 + 3) * 128 + rr] = pa0.w;
        As[(k4 * 4 + 0) * 128 + rr + 64] = pa1.x;
        As[(k4 * 4 + 1) * 128 + rr + 64] = pa1.y;
        As[(k4 * 4 + 2) * 128 + rr + 64] = pa1.z;
        As[(k4 * 4 + 3) * 128 + rr + 64] = pa1.w;
        Bs[(k4 * 4 + 0) * 128 + rr] = pb0.x;
        Bs[(k4 * 4 + 1) * 128 + rr] = pb0.y;
        Bs[(k4 * 4 + 2) * 128 + rr] = pb0.z;
        Bs[(k4 * 4 + 3) * 128 + rr] = pb0.w;
        Bs[(k4 * 4 + 0) * 128 + rr + 64] = pb1.x;
        Bs[(k4 * 4 + 1) * 128 + rr + 64] = pb1.y;
        Bs[(k4 * 4 + 2) * 128 + rr + 64] = pb1.z;
        Bs[(k4 * 4 + 3) * 128 + rr + 64] = pb1.w;
        __syncthreads();

        if (kt < 63) {
            const int off = (kt + 1) * 16;
            pa0 = *(const float4*)(Abase + off);
            pa1 = *(const float4*)(Abase + (size_t)64 * 1024 + off);
            pb0 = *(const float4*)(Bbase + off);
            pb1 = *(const float4*)(Bbase + (size_t)64 * 1024 + off);
        }

#pragma unroll
        for (int k = 0; k < 16; ++k) {
            const float4 a0 = *(const float4*)(As + k * 128 + ty * 4);
            const float4 a1 = *(const float4*)(As + k * 128 + 64 + ty * 4);
            const ulonglong2 bpa = *(const ulonglong2*)(Bs + k * 128 + tx * 4);
            const ulonglong2 bpb = *(const ulonglong2*)(Bs + k * 128 + 64 + tx * 4);
            ull ad[8];
            ad[0] = pk2(a0.x, a0.x); ad[1] = pk2(a0.y, a0.y);
            ad[2] = pk2(a0.z, a0.z); ad[3] = pk2(a0.w, a0.w);
            ad[4] = pk2(a1.x, a1.x); ad[5] = pk2(a1.y, a1.y);
            ad[6] = pk2(a1.z, a1.z); ad[7] = pk2(a1.w, a1.w);
            const ull bp[4] = {bpa.x, bpa.y, bpb.x, bpb.y};
#pragma unroll
            for (int ii = 0; ii < 8; ++ii)
#pragma unroll
                for (int jj = 0; jj < 4; ++jj)
                    acc[ii][jj] = fma2(ad[ii], bp[jj], acc[ii][jj]);
        }
        __syncthreads();
    }
    // Epilogue with bias
#pragma unroll
    for (int jh = 0; jh < 2; ++jh) {
        const int col = bn * 128 + jh * 64 + tx * 4;
        const float4 bb = *(const float4*)(bias + col);
#pragma unroll
        for (int ii = 0; ii < 8; ++ii) {
            const int row = bm * 128 + ((ii < 4) ? (ty * 4 + ii) : (64 + ty * 4 + ii - 4));
            const float2 c01 = upk(acc[ii][jh * 2 + 0]);
            const float2 c23 = upk(acc[ii][jh * 2 + 1]);
            float4 o;
            o.x = c01.x + bb.x;
            o.y = c01.y + bb.y;
            o.z = c23.x + bb.z;
            o.w = c23.y + bb.w;
            *(float4*)(C + (size_t)row * 1024 + col) = o;
        }
    }
}

// Fused Q/K/V projections: blockIdx.z selects the operand set.
__global__ __launch_bounds__(256, 2)
void gemm_qkv_kernel(const float* __restrict__ q, const float* __restrict__ k,
                     const float* __restrict__ v,
                     const float* __restrict__ Wq, const float* __restrict__ bq,
                     const float* __restrict__ Wk, const float* __restrict__ bk,
                     const float* __restrict__ Wv, const float* __restrict__ bv,
                     float* __restrict__ Qp, float* __restrict__ Kp, float* __restrict__ Vp)
{
    const int which = blockIdx.z;
    const float* A    = (which == 0) ? q  : (which == 1) ? k  : v;
    const float* B    = (which == 0) ? Wq : (which == 1) ? Wk : Wv;
    const float* bias = (which == 0) ? bq : (which == 1) ? bk : bv;
    float*       C    = (which == 0) ? Qp : (which == 1) ? Kp : Vp;
    gemm_body(A, B, bias, C, blockIdx.y, blockIdx.x);
}

__global__ __launch_bounds__(256, 2)
void gemm_o_kernel(const float* __restrict__ A, const float* __restrict__ B,
                   const float* __restrict__ bias, float* __restrict__ C)
{
    gemm_body(A, B, bias, C, blockIdx.y, blockIdx.x);
}

// ---------------------------------------------------------------------------
// Fused sparse attention: one block per (n, h, 8-query tile), 256 threads,
// ~107KB smem -> 2 blocks/SM. Per-row exact radix select of the K_SEL-th
// largest score -> threshold; masked softmax; P @ V.
// ---------------------------------------------------------------------------
#define SC_FLOATS   (ROWS * SCS)        // 16416
#define KV_FLOATS   (CHUNK * KSTR)      // 8320 (V uses stride 64 inside)
#define QT_FLOATS   512                 // 64 e x 4 row-pair ull = 256 ull
#define WORK_FLOATS 2048                // hist(8KB) / qs(2KB) / stage(6KB)
#define ATTN_SMEM_FLOATS (SC_FLOATS + KV_FLOATS + QT_FLOATS + WORK_FLOATS + 32)
#define ATTN_SMEM_BYTES  (ATTN_SMEM_FLOATS * 4)

__global__ __launch_bounds__(256, 2)
void attn_kernel()
{
    extern __shared__ float sm[];
    float*    sc   = sm;                                // [8][SCS] scores -> weights
    float*    kv   = sm + SC_FLOATS;                    // K [128][65] / V [128][64]
    ull*      qt2  = (ull*)(sm + SC_FLOATS + KV_FLOATS);// [64][4] q row-pairs, scaled
    float*    work = sm + SC_FLOATS + KV_FLOATS + QT_FLOATS;
    unsigned* hist   = (unsigned*)work;                 // 8 warps x 256 bins
    ull*      stage  = (ull*)work;                      // phase-4 partials (6KB)
    float*    small_ = work + WORK_FLOATS;
    unsigned* s_tkey = (unsigned*)small_;               // [8]
    unsigned* s_umax = s_tkey + 8;                      // [8]
    float*    s_sum  = (float*)(s_umax + 8);            // [8]

    const int tid = threadIdx.x;
    const int n = blockIdx.z, h = blockIdx.y;
    const int l0 = blockIdx.x * ROWS;

    // ---- Load Q (8 rows x 64 e) into work, then pack row-pairs into qt2 ----
    {
        float* qs = work;   // [8][64]
        if (tid < 128) {
            const int row = tid >> 4, e4 = tid & 15;
            const float4 q = *(const float4*)(g_Qp + (size_t)((l0 + row) * 2 + n) * 1024 + h * 64 + e4 * 4);
            *(float4*)(qs + row * 64 + e4 * 4) = q;
        }
        __syncthreads();
        {
            const int e = tid >> 2, rp = tid & 3;       // 64 e x 4 row-pairs
            qt2[e * 4 + rp] = pk2(qs[(2 * rp) * 64 + e] * 0.125f,
                                  (2 * rp + 1 < ROWS ? qs[(2 * rp + 1) * 64 + e] : 0.0f) * 0.125f);
        }
    }
    __syncthreads();

    // ---- Phase 1: scores = Q K^T; thread = 1 key col x 4 rows (2 f32x2 pairs) ----
    {
        const int col = tid & 127;       // key within chunk
        const int rg  = tid >> 7;        // 0/1 -> rows rg*4 .. rg*4+3
        for (int s0 = 0; s0 < S_DIM; s0 += CHUNK) {
            // coalesced K load: lanes along e; smem s-major stride 65
#pragma unroll
            for (int i = 0; i < 8; ++i) {
                const int idx = i * 256 + tid;
                const int sr = idx >> 4, e4 = idx & 15;
                const float4 k = *(const float4*)(g_Kp + (size_t)((s0 + sr) * 2 + n) * 1024 + h * 64 + e4 * 4);
                float* dst = kv + sr * KSTR + e4 * 4;
                dst[0] = k.x; dst[1] = k.y; dst[2] = k.z; dst[3] = k.w;
            }
            __syncthreads();
            ull a0 = 0, a1 = 0;
            const float* kp = kv + col * KSTR;
            const ull* qp = qt2 + 2 * rg;
#pragma unroll 8
            for (int e = 0; e < 64; ++e) {
                const float kk = kp[e];
                const ull kd = pk2(kk, kk);
                const ulonglong2 q2 = *(const ulonglong2*)(qp + e * 4);
                a0 = fma2(q2.x, kd, a0);
                a1 = fma2(q2.y, kd, a1);
            }
            const int r0 = rg * 4;
            float* sp = sc + s0 + col;
            float2 t;
            t = upk(a0); sp[(r0 + 0) * SCS] = t.x; sp[(r0 + 1) * SCS] = t.y;
            t = upk(a1); sp[(r0 + 2) * SCS] = t.x; sp[(r0 + 3) * SCS] = t.y;
            __syncthreads();
        }
    }

    // ---- Phase 2: per-row exact radix select, one warp per row ----
    {
        const int wid = tid >> 5, lane = tid & 31;
        const int row = wid;
        unsigned* hw = hist + wid * 256;
        const float* srow = sc + row * SCS;
        unsigned km = 0;
#pragma unroll 8
        for (int j = 0; j < 64; ++j) {
            const unsigned k = f2key(srow[lane + 32 * j]);
            km = (k > km) ? k : km;
        }
#pragma unroll
        for (int o = 16; o > 0; o >>= 1) {
            const unsigned v = __shfl_xor_sync(0xffffffffu, km, o);
            km = (v > km) ? v : km;
        }
        unsigned prefix = 0;
        unsigned T = T_SEL;
#pragma unroll
        for (int b = 3; b >= 0; --b) {
            for (int i = lane; i < 256; i += 32) hw[i] = 0;
            __syncwarp();
            const unsigned himask = (b == 3) ? 0u : (0xFFFFFFFFu << ((b + 1) * 8));
            for (int j = 0; j < 64; ++j) {
                const unsigned key = f2key(srow[lane + 32 * j]);
                const bool act = ((key & himask) == prefix);
                const unsigned bin = (key >> (b * 8)) & 255;
                const unsigned tag = act ? bin : (0x100u + (unsigned)lane);
                const unsigned grp = __match_any_sync(0xffffffffu, tag);
                if (act && lane == (__ffs(grp) - 1))
                    atomicAdd(&hw[bin], (unsigned)__popc(grp));
            }
            __syncwarp();
            unsigned c[8], lsum = 0;
#pragma unroll
            for (int i = 0; i < 8; ++i) { c[i] = hw[lane * 8 + i]; lsum += c[i]; }
            unsigned inc = lsum;
#pragma unroll
            for (int o = 1; o < 32; o <<= 1) {
                const unsigned v = __shfl_up_sync(0xffffffffu, inc, o);
                if (lane >= o) inc += v;
            }
            const unsigned exl = inc - lsum;
            const bool own = (T >= exl) && (T < exl + lsum);
            const unsigned bal = __ballot_sync(0xffffffffu, own);
            const int src = __ffs(bal) - 1;
            unsigned bsel = 0, nT = 0;
            if (own) {
                unsigned cum = exl;
#pragma unroll
                for (int i = 0; i < 8; ++i) {
                    if (T < cum + c[i]) { bsel = (unsigned)(lane * 8 + i); nT = T - cum; break; }
                    cum += c[i];
                }
            }
            bsel = __shfl_sync(0xffffffffu, bsel, src);
            nT   = __shfl_sync(0xffffffffu, nT, src);
            prefix |= bsel << (b * 8);
            T = nT;
            __syncwarp();
        }
        if (lane == 0) { s_tkey[row] = prefix; s_umax[row] = km; }
    }
    __syncthreads();

    // ---- Phase 3: masked exp weights + row sums (one warp per row) ----
    {
        const int row = tid >> 5, lane = tid & 31;
        const unsigned tk = s_tkey[row];
        const float m = key2f(s_umax[row]);
        float lsum = 0.0f;
        float* srow = sc + row * SCS;
#pragma unroll 4
        for (int j = 0; j < 64; ++j) {
            const float x = srow[j * 32 + lane];
            float w = 0.0f;
            if (f2key(x) >= tk) w = fexp(x - m);
            srow[j * 32 + lane] = w;
            lsum += w;
        }
#pragma unroll
        for (int o = 16; o > 0; o >>= 1)
            lsum += __shfl_xor_sync(0xffffffffu, lsum, o);
        if (lane == 0) s_sum[row] = lsum;
    }
    __syncthreads();

    // ---- Phase 4: O = W @ V; thread = 2 rows x 4 d, 4-way s-split ----
    const int dq  = tid & 15;            // d quad
    const int rgp = (tid >> 4) & 3;      // row pair: rows 2rgp, 2rgp+1
    const int g   = tid >> 6;            // s-split 0..3
    ull acc[4] = {0, 0, 0, 0};           // packed (row0,row1) per d
    for (int s0 = 0; s0 < S_DIM; s0 += CHUNK) {
        // coalesced V load, s-major stride 64
#pragma unroll
        for (int i = 0; i < 8; ++i) {
            const int idx = i * 256 + tid;
            const int sr = idx >> 4, d4 = idx & 15;
            const float4 v = *(const float4*)(g_Vp + (size_t)((s0 + sr) * 2 + n) * 1024 + h * 64 + d4 * 4);
            *(float4*)(kv + sr * 64 + d4 * 4) = v;
        }
        __syncthreads();
        const float* w0 = sc + (2 * rgp) * SCS + s0 + g * 32;
        const float* w1 = w0 + SCS;
        const float* vp = kv + (g * 32) * 64 + dq * 4;
#pragma unroll 8
        for (int sl = 0; sl < 32; ++sl) {
            const ull wp = pk2(w0[sl], w1[sl]);
            const float4 v = *(const float4*)(vp + sl * 64);
            acc[0] = fma2(wp, pk2(v.x, v.x), acc[0]);
            acc[1] = fma2(wp, pk2(v.y, v.y), acc[1]);
            acc[2] = fma2(wp, pk2(v.z, v.z), acc[2]);
            acc[3] = fma2(wp, pk2(v.w, v.w), acc[3]);
        }
        __syncthreads();
    }

    // ---- Phase 5: cross-split reduce (stage aliases work), normalize, scatter ----
    const int slot = rgp * 16 + dq;      // 0..63
    if (g > 0) {
#pragma unroll
        for (int j = 0; j < 4; ++j)
            stage[((g - 1) * 64 + slot) * 4 + j] = acc[j];
    }
    __syncthreads();
    if (g == 0) {
#pragma unroll
        for (int gg = 0; gg < 3; ++gg)
#pragma unroll
            for (int j = 0; j < 4; ++j)
                acc[j] = add2(acc[j], stage[(gg * 64 + slot) * 4 + j]);
        const float inv0 = 1.0f / s_sum[2 * rgp];
        const float inv1 = 1.0f / s_sum[2 * rgp + 1];
        float* o0 = g_O + (size_t)((l0 + 2 * rgp)     * 2 + n) * 1024 + h;  // + d*16
        float* o1 = g_O + (size_t)((l0 + 2 * rgp + 1) * 2 + n) * 1024 + h;
#pragma unroll
        for (int j = 0; j < 4; ++j) {
            const float2 r = upk(acc[j]);
            o0[(dq * 4 + j) * 16] = r.x * inv0;
            o1[(dq * 4 + j) * 16] = r.y * inv1;
        }
    }
}

// ---------------------------------------------------------------------------
// Launch
// ---------------------------------------------------------------------------
extern "C" void kernel_launch(void* const* d_in, const int* in_sizes, int n_in,
                              void* d_out, int out_size)
{
    (void)in_sizes; (void)n_in; (void)out_size;
    const float* query = (const float*)d_in[0];
    const float* key   = (const float*)d_in[1];
    const float* value = (const float*)d_in[2];
    const float* Wq = (const float*)d_in[3];
    const float* bq = (const float*)d_in[4];
    const float* Wk = (const float*)d_in[5];
    const float* bk = (const float*)d_in[6];
    const float* Wv = (const float*)d_in[7];
    const float* bv = (const float*)d_in[8];
    const float* Wo = (const float*)d_in[9];
    const float* bo = (const float*)d_in[10];

    float *Qp, *Kp, *Vp, *O;
    cudaGetSymbolAddress((void**)&Qp, g_Qp);
    cudaGetSymbolAddress((void**)&Kp, g_Kp);
    cudaGetSymbolAddress((void**)&Vp, g_Vp);
    cudaGetSymbolAddress((void**)&O,  g_O);

    cudaFuncSetAttribute(attn_kernel, cudaFuncAttributeMaxDynamicSharedMemorySize,
                         ATTN_SMEM_BYTES);

    gemm_qkv_kernel<<<dim3(8, 32, 3), 256>>>(query, key, value,
                                             Wq, bq, Wk, bk, Wv, bv,
                                             Qp, Kp, Vp);

    attn_kernel<<<dim3(L_DIM / ROWS, H_N, N_B), 256, ATTN_SMEM_BYTES>>>();

    gemm_o_kernel<<<dim3(8, 32, 1), 256>>>(O, Wo, bo, (float*)d_out);
}

// round 12
// speedup vs baseline: 1.4205x; 1.1604x over previous
#include <cuda_runtime.h>
#include <cstdint>

typedef unsigned long long ull;

// Problem constants
#define L_DIM   2048
#define N_B     2
#define E_DIM   1024
#define H_N     16
#define D_H     64
#define S_DIM   2048
#define K_SEL   1176              // int(2048 * sigmoid(0.3))
#define T_SEL   (S_DIM - K_SEL)   // 872: 0-based ascending rank of threshold

// Scratch (static device arrays are allowed; cudaMalloc is not)
__device__ float g_Qp[4096 * 1024];     // [n][h][l][d]
__device__ float g_Kp[4096 * 1024];     // [n][h][l][d]
__device__ float g_Vp[4096 * 1024];     // [n][h][l][d]
__device__ float g_O [4096 * 1024];     // [(l,n)][d*16+h]
__device__ float g_S [33554432];        // [h_local<8][l][s] scores (128 MB)

// ---------------------------------------------------------------------------
// Helpers
// ---------------------------------------------------------------------------
__device__ __forceinline__ unsigned f2key(float f) {
    unsigned u = __float_as_uint(f);
    return (u & 0x80000000u) ? ~u : (u | 0x80000000u);
}
__device__ __forceinline__ float key2f(unsigned k) {
    unsigned u = (k & 0x80000000u) ? (k ^ 0x80000000u) : ~k;
    return __uint_as_float(u);
}
// Fast e^x for x <= 0 (poly exp2, ~1e-7 rel err). Avoids MUFU bottleneck.
__device__ __forceinline__ float fexp(float x) {
    float y = x * 1.4426950408889634f;
    y = fmaxf(y, -120.0f);
    float fl = floorf(y);
    float f  = y - fl;
    float p  =             1.53533619e-4f;
    p = fmaf(p, f, 1.33988744e-3f);
    p = fmaf(p, f, 9.61843736e-3f);
    p = fmaf(p, f, 5.55033247e-2f);
    p = fmaf(p, f, 2.40226479e-1f);
    p = fmaf(p, f, 6.93147203e-1f);
    p = fmaf(p, f, 1.0f);
    return p * __int_as_float(((int)fl + 127) << 23);
}

// --- packed f32x2 ops (Blackwell, sm_100+) ---
__device__ __forceinline__ ull pk2(float a, float b) {
    ull r;
    asm("mov.b64 %0, {%1, %2};" : "=l"(r) : "r"(__float_as_uint(a)), "r"(__float_as_uint(b)));
    return r;
}
__device__ __forceinline__ ull fma2(ull a, ull b, ull c) {
    ull d;
    asm("fma.rn.f32x2 %0, %1, %2, %3;" : "=l"(d) : "l"(a), "l"(b), "l"(c));
    return d;
}
__device__ __forceinline__ float2 upk(ull v) {
    unsigned lo, hi;
    asm("mov.b64 {%0, %1}, %2;" : "=r"(lo), "=r"(hi) : "l"(v));
    return make_float2(__uint_as_float(lo), __uint_as_float(hi));
}

// ---------------------------------------------------------------------------
// Projection GEMM: C = A[4096,1024] @ W^T + bias. SCATTER=true writes the
// result into [n][h][l][d] layout; false writes row-major (final output).
// BM=BN=128, BK=16, 256 threads, 8x8 micro via 32 FFMA2, reg prefetch.
// ---------------------------------------------------------------------------
template <bool SCATTER>
__device__ __forceinline__
void gemm_body(const float* __restrict__ A, const float* __restrict__ B,
               const float* __restrict__ bias, float* __restrict__ C,
               int bm, int bn)
{
    __shared__ float As[16 * 128];
    __shared__ float Bs[16 * 128];
    const int tid = threadIdx.x;
    const int ty = tid >> 4, tx = tid & 15;
    const int rr = tid >> 2, k4 = tid & 3;

    ull acc[8][4];
#pragma unroll
    for (int i = 0; i < 8; ++i)
#pragma unroll
        for (int j = 0; j < 4; ++j) acc[i][j] = 0ull;

    const float* Abase = A + (size_t)(bm * 128 + rr) * 1024 + k4 * 4;
    const float* Bbase = B + (size_t)(bn * 128 + rr) * 1024 + k4 * 4;

    float4 pa0 = *(const float4*)(Abase);
    float4 pa1 = *(const float4*)(Abase + (size_t)64 * 1024);
    float4 pb0 = *(const float4*)(Bbase);
    float4 pb1 = *(const float4*)(Bbase + (size_t)64 * 1024);

    for (int kt = 0; kt < 64; ++kt) {
        As[(k4 * 4 + 0) * 128 + rr] = pa0.x;
        As[(k4 * 4 + 1) * 128 + rr] = pa0.y;
        As[(k4 * 4 + 2) * 128 + rr] = pa0.z;
        As[(k4 * 4 + 3) * 128 + rr] = pa0.w;
        As[(k4 * 4 + 0) * 128 + rr + 64] = pa1.x;
        As[(k4 * 4 + 1) * 128 + rr + 64] = pa1.y;
        As[(k4 * 4 + 2) * 128 + rr + 64] = pa1.z;
        As[(k4 * 4 + 3) * 128 + rr + 64] = pa1.w;
        Bs[(k4 * 4 + 0) * 128 + rr] = pb0.x;
        Bs[(k4 * 4 + 1) * 128 + rr] = pb0.y;
        Bs[(k4 * 4 + 2) * 128 + rr] = pb0.z;
        Bs[(k4 * 4 + 3) * 128 + rr] = pb0.w;
        Bs[(k4 * 4 + 0) * 128 + rr + 64] = pb1.x;
        Bs[(k4 * 4 + 1) * 128 + rr + 64] = pb1.y;
        Bs[(k4 * 4 + 2) * 128 + rr + 64] = pb1.z;
        Bs[(k4 * 4 + 3) * 128 + rr + 64] = pb1.w;
        __syncthreads();

        if (kt < 63) {
            const int off = (kt + 1) * 16;
            pa0 = *(const float4*)(Abase + off);
            pa1 = *(const float4*)(Abase + (size_t)64 * 1024 + off);
            pb0 = *(const float4*)(Bbase + off);
            pb1 = *(const float4*)(Bbase + (size_t)64 * 1024 + off);
        }

#pragma unroll
        for (int k = 0; k < 16; ++k) {
            const float4 a0 = *(const float4*)(As + k * 128 + ty * 4);
            const float4 a1 = *(const float4*)(As + k * 128 + 64 + ty * 4);
            const ulonglong2 bpa = *(const ulonglong2*)(Bs + k * 128 + tx * 4);
            const ulonglong2 bpb = *(const ulonglong2*)(Bs + k * 128 + 64 + tx * 4);
            ull ad[8];
            ad[0] = pk2(a0.x, a0.x); ad[1] = pk2(a0.y, a0.y);
            ad[2] = pk2(a0.z, a0.z); ad[3] = pk2(a0.w, a0.w);
            ad[4] = pk2(a1.x, a1.x); ad[5] = pk2(a1.y, a1.y);
            ad[6] = pk2(a1.z, a1.z); ad[7] = pk2(a1.w, a1.w);
            const ull bp[4] = {bpa.x, bpa.y, bpb.x, bpb.y};
#pragma unroll
            for (int ii = 0; ii < 8; ++ii)
#pragma unroll
                for (int jj = 0; jj < 4; ++jj)
                    acc[ii][jj] = fma2(ad[ii], bp[jj], acc[ii][jj]);
        }
        __syncthreads();
    }
    // Epilogue with bias
#pragma unroll
    for (int jh = 0; jh < 2; ++jh) {
        const int col = bn * 128 + jh * 64 + tx * 4;
        const float4 bb = *(const float4*)(bias + col);
#pragma unroll
        for (int ii = 0; ii < 8; ++ii) {
            const int row = bm * 128 + ((ii < 4) ? (ty * 4 + ii) : (64 + ty * 4 + ii - 4));
            const float2 c01 = upk(acc[ii][jh * 2 + 0]);
            const float2 c23 = upk(acc[ii][jh * 2 + 1]);
            float4 o;
            o.x = c01.x + bb.x;
            o.y = c01.y + bb.y;
            o.z = c23.x + bb.z;
            o.w = c23.y + bb.w;
            if (SCATTER) {
                // row=(l,n), col=(h,d) -> [n][h][l][d]
                const int l = row >> 1, nn = row & 1;
                const int h = bn * 2 + jh, d = tx * 4;
                *(float4*)(C + ((size_t)(nn * 16 + h) * 2048 + l) * 64 + d) = o;
            } else {
                *(float4*)(C + (size_t)row * 1024 + col) = o;
            }
        }
    }
}

__global__ __launch_bounds__(256, 2)
void gemm_qkv_kernel(const float* __restrict__ q, const float* __restrict__ k,
                     const float* __restrict__ v,
                     const float* __restrict__ Wq, const float* __restrict__ bq,
                     const float* __restrict__ Wk, const float* __restrict__ bk,
                     const float* __restrict__ Wv, const float* __restrict__ bv,
                     float* __restrict__ Qp, float* __restrict__ Kp, float* __restrict__ Vp)
{
    const int which = blockIdx.z;
    const float* A    = (which == 0) ? q  : (which == 1) ? k  : v;
    const float* B    = (which == 0) ? Wq : (which == 1) ? Wk : Wv;
    const float* bias = (which == 0) ? bq : (which == 1) ? bk : bv;
    float*       C    = (which == 0) ? Qp : (which == 1) ? Kp : Vp;
    gemm_body<true>(A, B, bias, C, blockIdx.y, blockIdx.x);
}

__global__ __launch_bounds__(256, 2)
void gemm_o_kernel(const float* __restrict__ A, const float* __restrict__ B,
                   const float* __restrict__ bias, float* __restrict__ C)
{
    gemm_body<false>(A, B, bias, C, blockIdx.y, blockIdx.x);
}

// ---------------------------------------------------------------------------
// QK^T for one (n, 8-head group): per-h GEMM  S = Q[2048,64] @ K^T * 0.125
// BM=BN=128, BK=16 x4, 256 threads, same micro-tiling as gemm_body.
// ---------------------------------------------------------------------------
__global__ __launch_bounds__(256, 2)
void qk_kernel(int n, int hbase)
{
    __shared__ float As[16 * 128];
    __shared__ float Bs[16 * 128];
    const int tid = threadIdx.x;
    const int hl = blockIdx.z, bm = blockIdx.y, bn = blockIdx.x;
    const int nh = n * 16 + hbase + hl;
    const int ty = tid >> 4, tx = tid & 15;
    const int rr = tid >> 2, k4 = tid & 3;

    const float* A = g_Qp + (size_t)nh * 131072;  // 2048*64
    const float* B = g_Kp + (size_t)nh * 131072;

    ull acc[8][4];
#pragma unroll
    for (int i = 0; i < 8; ++i)
#pragma unroll
        for (int j = 0; j < 4; ++j) acc[i][j] = 0ull;

    const float* Abase = A + (size_t)(bm * 128 + rr) * 64 + k4 * 4;
    const float* Bbase = B + (size_t)(bn * 128 + rr) * 64 + k4 * 4;

    float4 pa0 = *(const float4*)(Abase);
    float4 pa1 = *(const float4*)(Abase + 64 * 64);
    float4 pb0 = *(const float4*)(Bbase);
    float4 pb1 = *(const float4*)(Bbase + 64 * 64);

#pragma unroll
    for (int kt = 0; kt < 4; ++kt) {
        As[(k4 * 4 + 0) * 128 + rr] = pa0.x;
        As[(k4 * 4 + 1) * 128 + rr] = pa0.y;
        As[(k4 * 4 + 2) * 128 + rr] = pa0.z;
        As[(k4 * 4 + 3) * 128 + rr] = pa0.w;
        As[(k4 * 4 + 0) * 128 + rr + 64] = pa1.x;
        As[(k4 * 4 + 1) * 128 + rr + 64] = pa1.y;
        As[(k4 * 4 + 2) * 128 + rr + 64] = pa1.z;
        As[(k4 * 4 + 3) * 128 + rr + 64] = pa1.w;
        Bs[(k4 * 4 + 0) * 128 + rr] = pb0.x;
        Bs[(k4 * 4 + 1) * 128 + rr] = pb0.y;
        Bs[(k4 * 4 + 2) * 128 + rr] = pb0.z;
        Bs[(k4 * 4 + 3) * 128 + rr] = pb0.w;
        Bs[(k4 * 4 + 0) * 128 + rr + 64] = pb1.x;
        Bs[(k4 * 4 + 1) * 128 + rr + 64] = pb1.y;
        Bs[(k4 * 4 + 2) * 128 + rr + 64] = pb1.z;
        Bs[(k4 * 4 + 3) * 128 + rr + 64] = pb1.w;
        __syncthreads();

        if (kt < 3) {
            const int off = (kt + 1) * 16;
            pa0 = *(const float4*)(Abase + off);
            pa1 = *(const float4*)(Abase + 64 * 64 + off);
            pb0 = *(const float4*)(Bbase + off);
            pb1 = *(const float4*)(Bbase + 64 * 64 + off);
        }

#pragma unroll
        for (int k = 0; k < 16; ++k) {
            const float4 a0 = *(const float4*)(As + k * 128 + ty * 4);
            const float4 a1 = *(const float4*)(As + k * 128 + 64 + ty * 4);
            const ulonglong2 bpa = *(const ulonglong2*)(Bs + k * 128 + tx * 4);
            const ulonglong2 bpb = *(const ulonglong2*)(Bs + k * 128 + 64 + tx * 4);
            ull ad[8];
            ad[0] = pk2(a0.x, a0.x); ad[1] = pk2(a0.y, a0.y);
            ad[2] = pk2(a0.z, a0.z); ad[3] = pk2(a0.w, a0.w);
            ad[4] = pk2(a1.x, a1.x); ad[5] = pk2(a1.y, a1.y);
            ad[6] = pk2(a1.z, a1.z); ad[7] = pk2(a1.w, a1.w);
            const ull bp[4] = {bpa.x, bpa.y, bpb.x, bpb.y};
#pragma unroll
            for (int ii = 0; ii < 8; ++ii)
#pragma unroll
                for (int jj = 0; jj < 4; ++jj)
                    acc[ii][jj] = fma2(ad[ii], bp[jj], acc[ii][jj]);
        }
        __syncthreads();
    }
    // Epilogue: scale by 1/sqrt(64) and write scores
    float* Sbase = g_S + (size_t)hl * 4194304;
#pragma unroll
    for (int jh = 0; jh < 2; ++jh) {
        const int col = bn * 128 + jh * 64 + tx * 4;
#pragma unroll
        for (int ii = 0; ii < 8; ++ii) {
            const int row = bm * 128 + ((ii < 4) ? (ty * 4 + ii) : (64 + ty * 4 + ii - 4));
            const float2 c01 = upk(acc[ii][jh * 2 + 0]);
            const float2 c23 = upk(acc[ii][jh * 2 + 1]);
            float4 o;
            o.x = c01.x * 0.125f;
            o.y = c01.y * 0.125f;
            o.z = c23.x * 0.125f;
            o.w = c23.y * 0.125f;
            *(float4*)(Sbase + (size_t)row * 2048 + col) = o;
        }
    }
}

// ---------------------------------------------------------------------------
// Select + softmax: one 256-thread block per score row (16384 blocks/pass).
// Row cached in registers (8 floats/thread). Exact block-level radix select
// of the rank-T_SEL key, then masked exp, block sum, write normalized weights.
// ---------------------------------------------------------------------------
__global__ __launch_bounds__(256)
void sel_kernel()
{
    __shared__ unsigned hist[256];
    __shared__ unsigned s_pfx, s_T, s_km;
    __shared__ float    f_red[8];
    __shared__ unsigned u_red[8];
    __shared__ float    s_inv;

    const int tid = threadIdx.x, lane = tid & 31, wid = tid >> 5;
    float* srow = g_S + (size_t)blockIdx.x * 2048;

    float v[8];
    unsigned key[8];
    {
        const float4 f0 = *(const float4*)(srow + tid * 8);
        const float4 f1 = *(const float4*)(srow + tid * 8 + 4);
        v[0] = f0.x; v[1] = f0.y; v[2] = f0.z; v[3] = f0.w;
        v[4] = f1.x; v[5] = f1.y; v[6] = f1.z; v[7] = f1.w;
#pragma unroll
        for (int i = 0; i < 8; ++i) key[i] = f2key(v[i]);
    }

    // block max of keys
    {
        unsigned km = key[0];
#pragma unroll
        for (int i = 1; i < 8; ++i) km = (key[i] > km) ? key[i] : km;
#pragma unroll
        for (int o = 16; o > 0; o >>= 1) {
            const unsigned t = __shfl_xor_sync(0xffffffffu, km, o);
            km = (t > km) ? t : km;
        }
        if (lane == 0) u_red[wid] = km;
        __syncthreads();
        if (tid == 0) {
            unsigned m = u_red[0];
#pragma unroll
            for (int i = 1; i < 8; ++i) m = (u_red[i] > m) ? u_red[i] : m;
            s_km = m;
        }
    }

    // 4-pass MSB-first byte radix select for ascending rank T_SEL
    unsigned prefix = 0, T = T_SEL;
#pragma unroll
    for (int b = 3; b >= 0; --b) {
        hist[tid] = 0;
        __syncthreads();
        const unsigned himask = (b == 3) ? 0u : (0xFFFFFFFFu << ((b + 1) * 8));
#pragma unroll
        for (int i = 0; i < 8; ++i) {
            const bool act = ((key[i] & himask) == prefix);
            const unsigned bin = (key[i] >> (b * 8)) & 255;
            const unsigned tag = act ? bin : (0x100u + (unsigned)lane);
            const unsigned grp = __match_any_sync(0xffffffffu, tag);
            if (act && lane == (__ffs(grp) - 1))
                atomicAdd(&hist[bin], (unsigned)__popc(grp));
        }
        __syncthreads();
        if (wid == 0) {
            unsigned c[8], lsum = 0;
#pragma unroll
            for (int i = 0; i < 8; ++i) { c[i] = hist[lane * 8 + i]; lsum += c[i]; }
            unsigned inc = lsum;
#pragma unroll
            for (int o = 1; o < 32; o <<= 1) {
                const unsigned t = __shfl_up_sync(0xffffffffu, inc, o);
                if (lane >= o) inc += t;
            }
            const unsigned exl = inc - lsum;
            if (T >= exl && T < exl + lsum) {   // exactly one lane owns
                unsigned cum = exl;
#pragma unroll
                for (int i = 0; i < 8; ++i) {
                    if (T < cum + c[i]) {
                        s_pfx = prefix | ((unsigned)(lane * 8 + i) << (b * 8));
                        s_T   = T - cum;
                        break;
                    }
                    cum += c[i];
                }
            }
        }
        __syncthreads();
        prefix = s_pfx;
        T = s_T;
        __syncthreads();
    }

    // masked exp + block sum
    const unsigned tk = prefix;
    const float m = key2f(s_km);
    float w[8];
    float lsum = 0.0f;
#pragma unroll
    for (int i = 0; i < 8; ++i) {
        w[i] = (key[i] >= tk) ? fexp(v[i] - m) : 0.0f;
        lsum += w[i];
    }
#pragma unroll
    for (int o = 16; o > 0; o >>= 1)
        lsum += __shfl_xor_sync(0xffffffffu, lsum, o);
    if (lane == 0) f_red[wid] = lsum;
    __syncthreads();
    if (tid == 0) {
        float t = 0.0f;
#pragma unroll
        for (int i = 0; i < 8; ++i) t += f_red[i];
        s_inv = 1.0f / t;
    }
    __syncthreads();
    const float inv = s_inv;

    float4 o0 = make_float4(w[0] * inv, w[1] * inv, w[2] * inv, w[3] * inv);
    float4 o1 = make_float4(w[4] * inv, w[5] * inv, w[6] * inv, w[7] * inv);
    *(float4*)(srow + tid * 8)     = o0;
    *(float4*)(srow + tid * 8 + 4) = o1;
}

// ---------------------------------------------------------------------------
// PV for one (n, 8-head group): per-h GEMM  O[2048,64] = W[2048,2048] @ V[2048,64]
// BM=128, BN=64 (full d), BK=128, 256 threads, 8l x 4d micro via FFMA2.
// W tile stored TRANSPOSED in smem (Wt[s][l], stride 129) so the compute
// loop reads 8 contiguous l values at fixed s (contraction over s).
// Output scattered to g_O[(l,n)][d*16+h] for the O projection.
// ---------------------------------------------------------------------------
#define PV_LSTR 129
#define PV_SMEM_BYTES ((128 * PV_LSTR + 128 * 64) * 4)

__global__ __launch_bounds__(256, 2)
void pv_kernel(int n, int hbase)
{
    extern __shared__ float psm[];
    float* Wt = psm;                 // [128 s][PV_LSTR l] (transposed)
    float* Vs = psm + 128 * PV_LSTR; // [128 s][64 d]

    const int tid = threadIdx.x;
    const int hl = blockIdx.y, bm = blockIdx.x;
    const int h = hbase + hl;
    const int nh = n * 16 + h;
    const int ty = tid >> 4, tx = tid & 15;   // ty: l octet, tx: d quad

    const float* Wrow  = g_S + (size_t)hl * 4194304 + (size_t)bm * 128 * 2048;
    const float* Vbase = g_Vp + (size_t)nh * 131072;

    ull acc[4][4];
#pragma unroll
    for (int i = 0; i < 4; ++i)
#pragma unroll
        for (int j = 0; j < 4; ++j) acc[i][j] = 0ull;

    for (int kt = 0; kt < 16; ++kt) {
        // W tile [128 l][128 s] from GMEM -> transposed Wt[s][l] in smem
#pragma unroll
        for (int i = 0; i < 16; ++i) {
            const int idx = i * 256 + tid;
            const int lr = idx >> 5, sq = idx & 31;
            const float4 w = *(const float4*)(Wrow + (size_t)lr * 2048 + kt * 128 + sq * 4);
            Wt[(sq * 4 + 0) * PV_LSTR + lr] = w.x;
            Wt[(sq * 4 + 1) * PV_LSTR + lr] = w.y;
            Wt[(sq * 4 + 2) * PV_LSTR + lr] = w.z;
            Wt[(sq * 4 + 3) * PV_LSTR + lr] = w.w;
        }
        // V tile [128 s][64 d]
#pragma unroll
        for (int i = 0; i < 8; ++i) {
            const int idx = i * 256 + tid;
            const int sr = idx >> 4, d4 = idx & 15;
            *(float4*)(Vs + sr * 64 + d4 * 4) =
                *(const float4*)(Vbase + (size_t)(kt * 128 + sr) * 64 + d4 * 4);
        }
        __syncthreads();

        const float* wb = Wt + ty * 8;
        const float* vb = Vs + tx * 4;
#pragma unroll 4
        for (int s = 0; s < 128; ++s) {
            const float* wr = wb + s * PV_LSTR;   // W[l = ty*8 .. ty*8+7][s]
            const ull p0 = pk2(wr[0], wr[1]);
            const ull p1 = pk2(wr[2], wr[3]);
            const ull p2 = pk2(wr[4], wr[5]);
            const ull p3 = pk2(wr[6], wr[7]);
            const float4 vv = *(const float4*)(vb + s * 64);
            const ull v0 = pk2(vv.x, vv.x);
            const ull v1 = pk2(vv.y, vv.y);
            const ull v2 = pk2(vv.z, vv.z);
            const ull v3 = pk2(vv.w, vv.w);
            acc[0][0] = fma2(p0, v0, acc[0][0]);
            acc[0][1] = fma2(p0, v1, acc[0][1]);
            acc[0][2] = fma2(p0, v2, acc[0][2]);
            acc[0][3] = fma2(p0, v3, acc[0][3]);
            acc[1][0] = fma2(p1, v0, acc[1][0]);
            acc[1][1] = fma2(p1, v1, acc[1][1]);
            acc[1][2] = fma2(p1, v2, acc[1][2]);
            acc[1][3] = fma2(p1, v3, acc[1][3]);
            acc[2][0] = fma2(p2, v0, acc[2][0]);
            acc[2][1] = fma2(p2, v1, acc[2][1]);
            acc[2][2] = fma2(p2, v2, acc[2][2]);
            acc[2][3] = fma2(p2, v3, acc[2][3]);
            acc[3][0] = fma2(p3, v0, acc[3][0]);
            acc[3][1] = fma2(p3, v1, acc[3][1]);
            acc[3][2] = fma2(p3, v2, acc[3][2]);
            acc[3][3] = fma2(p3, v3, acc[3][3]);
        }
        __syncthreads();
    }

    // Epilogue: scatter to g_O[(l,n)][d*16+h]
#pragma unroll
    for (int lp = 0; lp < 4; ++lp) {
        const int l0 = bm * 128 + ty * 8 + lp * 2;
        float* o0 = g_O + (size_t)(l0 * 2 + n) * 1024 + h;
        float* o1 = g_O + (size_t)((l0 + 1) * 2 + n) * 1024 + h;
#pragma unroll
        for (int j = 0; j < 4; ++j) {
            const float2 r = upk(acc[lp][j]);
            const int d = tx * 4 + j;
            o0[d * 16] = r.x;
            o1[d * 16] = r.y;
        }
    }
}

// ---------------------------------------------------------------------------
// Launch
// ---------------------------------------------------------------------------
extern "C" void kernel_launch(void* const* d_in, const int* in_sizes, int n_in,
                              void* d_out, int out_size)
{
    (void)in_sizes; (void)n_in; (void)out_size;
    const float* query = (const float*)d_in[0];
    const float* key   = (const float*)d_in[1];
    const float* value = (const float*)d_in[2];
    const float* Wq = (const float*)d_in[3];
    const float* bq = (const float*)d_in[4];
    const float* Wk = (const float*)d_in[5];
    const float* bk = (const float*)d_in[6];
    const float* Wv = (const float*)d_in[7];
    const float* bv = (const float*)d_in[8];
    const float* Wo = (const float*)d_in[9];
    const float* bo = (const float*)d_in[10];

    float *Qp, *Kp, *Vp, *O;
    cudaGetSymbolAddress((void**)&Qp, g_Qp);
    cudaGetSymbolAddress((void**)&Kp, g_Kp);
    cudaGetSymbolAddress((void**)&Vp, g_Vp);
    cudaGetSymbolAddress((void**)&O,  g_O);

    cudaFuncSetAttribute(pv_kernel, cudaFuncAttributeMaxDynamicSharedMemorySize,
                         PV_SMEM_BYTES);

    gemm_qkv_kernel<<<dim3(8, 32, 3), 256>>>(query, key, value,
                                             Wq, bq, Wk, bk, Wv, bv,
                                             Qp, Kp, Vp);

    for (int np = 0; np < 4; ++np) {
        const int n = np >> 1, hbase = (np & 1) * 8;
        qk_kernel<<<dim3(16, 16, 8), 256>>>(n, hbase);
        sel_kernel<<<16384, 256>>>();
        pv_kernel<<<dim3(16, 8), 256, PV_SMEM_BYTES>>>(n, hbase);
    }

    gemm_o_kernel<<<dim3(8, 32), 256>>>(O, Wo, bo, (float*)d_out);
}

// round 13
// speedup vs baseline: 1.4347x; 1.0100x over previous
#include <cuda_runtime.h>
#include <cstdint>

typedef unsigned long long ull;

// Problem constants
#define L_DIM   2048
#define N_B     2
#define E_DIM   1024
#define H_N     16
#define D_H     64
#define S_DIM   2048
#define K_SEL   1176              // int(2048 * sigmoid(0.3))
#define T_SEL   (S_DIM - K_SEL)   // 872: 0-based ascending rank of threshold

// Scratch (static device arrays are allowed; cudaMalloc is not)
__device__ float g_Qp[4096 * 1024];     // [n][h][l][d]
__device__ float g_Kp[4096 * 1024];     // [n][h][l][d]
__device__ float g_Vp[4096 * 1024];     // [n][h][l][d]
__device__ float g_O [4096 * 1024];     // [(l,n)][d*16+h]
__device__ float g_S [67108864];        // [h][l][s] scores for ONE n (256 MB)

// ---------------------------------------------------------------------------
// Helpers
// ---------------------------------------------------------------------------
__device__ __forceinline__ unsigned f2key(float f) {
    unsigned u = __float_as_uint(f);
    return (u & 0x80000000u) ? ~u : (u | 0x80000000u);
}
__device__ __forceinline__ float key2f(unsigned k) {
    unsigned u = (k & 0x80000000u) ? (k ^ 0x80000000u) : ~k;
    return __uint_as_float(u);
}
// Fast e^x for x <= 0 (poly exp2, ~1e-7 rel err). Avoids MUFU bottleneck.
__device__ __forceinline__ float fexp(float x) {
    float y = x * 1.4426950408889634f;
    y = fmaxf(y, -120.0f);
    float fl = floorf(y);
    float f  = y - fl;
    float p  =             1.53533619e-4f;
    p = fmaf(p, f, 1.33988744e-3f);
    p = fmaf(p, f, 9.61843736e-3f);
    p = fmaf(p, f, 5.55033247e-2f);
    p = fmaf(p, f, 2.40226479e-1f);
    p = fmaf(p, f, 6.93147203e-1f);
    p = fmaf(p, f, 1.0f);
    return p * __int_as_float(((int)fl + 127) << 23);
}

// --- packed f32x2 ops (Blackwell, sm_100+) ---
__device__ __forceinline__ ull pk2(float a, float b) {
    ull r;
    asm("mov.b64 %0, {%1, %2};" : "=l"(r) : "r"(__float_as_uint(a)), "r"(__float_as_uint(b)));
    return r;
}
__device__ __forceinline__ ull fma2(ull a, ull b, ull c) {
    ull d;
    asm("fma.rn.f32x2 %0, %1, %2, %3;" : "=l"(d) : "l"(a), "l"(b), "l"(c));
    return d;
}
__device__ __forceinline__ float2 upk(ull v) {
    unsigned lo, hi;
    asm("mov.b64 {%0, %1}, %2;" : "=r"(lo), "=r"(hi) : "l"(v));
    return make_float2(__uint_as_float(lo), __uint_as_float(hi));
}

// ---------------------------------------------------------------------------
// Projection GEMM: C = A[4096,1024] @ W^T + bias. SCATTER=true writes the
// result into [n][h][l][d] layout; false writes row-major (final output).
// BM=BN=128, BK=16, 256 threads, 8x8 micro via 32 FFMA2, reg prefetch.
// ---------------------------------------------------------------------------
template <bool SCATTER>
__device__ __forceinline__
void gemm_body(const float* __restrict__ A, const float* __restrict__ B,
               const float* __restrict__ bias, float* __restrict__ C,
               int bm, int bn)
{
    __shared__ float As[16 * 128];
    __shared__ float Bs[16 * 128];
    const int tid = threadIdx.x;
    const int ty = tid >> 4, tx = tid & 15;
    const int rr = tid >> 2, k4 = tid & 3;

    ull acc[8][4];
#pragma unroll
    for (int i = 0; i < 8; ++i)
#pragma unroll
        for (int j = 0; j < 4; ++j) acc[i][j] = 0ull;

    const float* Abase = A + (size_t)(bm * 128 + rr) * 1024 + k4 * 4;
    const float* Bbase = B + (size_t)(bn * 128 + rr) * 1024 + k4 * 4;

    float4 pa0 = *(const float4*)(Abase);
    float4 pa1 = *(const float4*)(Abase + (size_t)64 * 1024);
    float4 pb0 = *(const float4*)(Bbase);
    float4 pb1 = *(const float4*)(Bbase + (size_t)64 * 1024);

    for (int kt = 0; kt < 64; ++kt) {
        As[(k4 * 4 + 0) * 128 + rr] = pa0.x;
        As[(k4 * 4 + 1) * 128 + rr] = pa0.y;
        As[(k4 * 4 + 2) * 128 + rr] = pa0.z;
        As[(k4 * 4 + 3) * 128 + rr] = pa0.w;
        As[(k4 * 4 + 0) * 128 + rr + 64] = pa1.x;
        As[(k4 * 4 + 1) * 128 + rr + 64] = pa1.y;
        As[(k4 * 4 + 2) * 128 + rr + 64] = pa1.z;
        As[(k4 * 4 + 3) * 128 + rr + 64] = pa1.w;
        Bs[(k4 * 4 + 0) * 128 + rr] = pb0.x;
        Bs[(k4 * 4 + 1) * 128 + rr] = pb0.y;
        Bs[(k4 * 4 + 2) * 128 + rr] = pb0.z;
        Bs[(k4 * 4 + 3) * 128 + rr] = pb0.w;
        Bs[(k4 * 4 + 0) * 128 + rr + 64] = pb1.x;
        Bs[(k4 * 4 + 1) * 128 + rr + 64] = pb1.y;
        Bs[(k4 * 4 + 2) * 128 + rr + 64] = pb1.z;
        Bs[(k4 * 4 + 3) * 128 + rr + 64] = pb1.w;
        __syncthreads();

        if (kt < 63) {
            const int off = (kt + 1) * 16;
            pa0 = *(const float4*)(Abase + off);
            pa1 = *(const float4*)(Abase + (size_t)64 * 1024 + off);
            pb0 = *(const float4*)(Bbase + off);
            pb1 = *(const float4*)(Bbase + (size_t)64 * 1024 + off);
        }

#pragma unroll
        for (int k = 0; k < 16; ++k) {
            const float4 a0 = *(const float4*)(As + k * 128 + ty * 4);
            const float4 a1 = *(const float4*)(As + k * 128 + 64 + ty * 4);
            const ulonglong2 bpa = *(const ulonglong2*)(Bs + k * 128 + tx * 4);
            const ulonglong2 bpb = *(const ulonglong2*)(Bs + k * 128 + 64 + tx * 4);
            ull ad[8];
            ad[0] = pk2(a0.x, a0.x); ad[1] = pk2(a0.y, a0.y);
            ad[2] = pk2(a0.z, a0.z); ad[3] = pk2(a0.w, a0.w);
            ad[4] = pk2(a1.x, a1.x); ad[5] = pk2(a1.y, a1.y);
            ad[6] = pk2(a1.z, a1.z); ad[7] = pk2(a1.w, a1.w);
            const ull bp[4] = {bpa.x, bpa.y, bpb.x, bpb.y};
#pragma unroll
            for (int ii = 0; ii < 8; ++ii)
#pragma unroll
                for (int jj = 0; jj < 4; ++jj)
                    acc[ii][jj] = fma2(ad[ii], bp[jj], acc[ii][jj]);
        }
        __syncthreads();
    }
    // Epilogue with bias
#pragma unroll
    for (int jh = 0; jh < 2; ++jh) {
        const int col = bn * 128 + jh * 64 + tx * 4;
        const float4 bb = *(const float4*)(bias + col);
#pragma unroll
        for (int ii = 0; ii < 8; ++ii) {
            const int row = bm * 128 + ((ii < 4) ? (ty * 4 + ii) : (64 + ty * 4 + ii - 4));
            const float2 c01 = upk(acc[ii][jh * 2 + 0]);
            const float2 c23 = upk(acc[ii][jh * 2 + 1]);
            float4 o;
            o.x = c01.x + bb.x;
            o.y = c01.y + bb.y;
            o.z = c23.x + bb.z;
            o.w = c23.y + bb.w;
            if (SCATTER) {
                // row=(l,n), col=(h,d) -> [n][h][l][d]
                const int l = row >> 1, nn = row & 1;
                const int h = bn * 2 + jh, d = tx * 4;
                *(float4*)(C + ((size_t)(nn * 16 + h) * 2048 + l) * 64 + d) = o;
            } else {
                *(float4*)(C + (size_t)row * 1024 + col) = o;
            }
        }
    }
}

__global__ __launch_bounds__(256, 2)
void gemm_qkv_kernel(const float* __restrict__ q, const float* __restrict__ k,
                     const float* __restrict__ v,
                     const float* __restrict__ Wq, const float* __restrict__ bq,
                     const float* __restrict__ Wk, const float* __restrict__ bk,
                     const float* __restrict__ Wv, const float* __restrict__ bv,
                     float* __restrict__ Qp, float* __restrict__ Kp, float* __restrict__ Vp)
{
    const int which = blockIdx.z;
    const float* A    = (which == 0) ? q  : (which == 1) ? k  : v;
    const float* B    = (which == 0) ? Wq : (which == 1) ? Wk : Wv;
    const float* bias = (which == 0) ? bq : (which == 1) ? bk : bv;
    float*       C    = (which == 0) ? Qp : (which == 1) ? Kp : Vp;
    gemm_body<true>(A, B, bias, C, blockIdx.y, blockIdx.x);
}

__global__ __launch_bounds__(256, 2)
void gemm_o_kernel(const float* __restrict__ A, const float* __restrict__ B,
                   const float* __restrict__ bias, float* __restrict__ C)
{
    gemm_body<false>(A, B, bias, C, blockIdx.y, blockIdx.x);
}

// ---------------------------------------------------------------------------
// QK^T for one n: per-h GEMM  S[2048,2048] = Q[2048,64] @ K^T * 0.125
// BM=BN=128, BK=16 x4, 256 threads, same micro-tiling as gemm_body.
// ---------------------------------------------------------------------------
__global__ __launch_bounds__(256, 2)
void qk_kernel(int n)
{
    __shared__ float As[16 * 128];
    __shared__ float Bs[16 * 128];
    const int tid = threadIdx.x;
    const int h = blockIdx.z, bm = blockIdx.y, bn = blockIdx.x;
    const int nh = n * 16 + h;
    const int ty = tid >> 4, tx = tid & 15;
    const int rr = tid >> 2, k4 = tid & 3;

    const float* A = g_Qp + (size_t)nh * 131072;  // 2048*64
    const float* B = g_Kp + (size_t)nh * 131072;

    ull acc[8][4];
#pragma unroll
    for (int i = 0; i < 8; ++i)
#pragma unroll
        for (int j = 0; j < 4; ++j) acc[i][j] = 0ull;

    const float* Abase = A + (size_t)(bm * 128 + rr) * 64 + k4 * 4;
    const float* Bbase = B + (size_t)(bn * 128 + rr) * 64 + k4 * 4;

    float4 pa0 = *(const float4*)(Abase);
    float4 pa1 = *(const float4*)(Abase + 64 * 64);
    float4 pb0 = *(const float4*)(Bbase);
    float4 pb1 = *(const float4*)(Bbase + 64 * 64);

#pragma unroll
    for (int kt = 0; kt < 4; ++kt) {
        As[(k4 * 4 + 0) * 128 + rr] = pa0.x;
        As[(k4 * 4 + 1) * 128 + rr] = pa0.y;
        As[(k4 * 4 + 2) * 128 + rr] = pa0.z;
        As[(k4 * 4 + 3) * 128 + rr] = pa0.w;
        As[(k4 * 4 + 0) * 128 + rr + 64] = pa1.x;
        As[(k4 * 4 + 1) * 128 + rr + 64] = pa1.y;
        As[(k4 * 4 + 2) * 128 + rr + 64] = pa1.z;
        As[(k4 * 4 + 3) * 128 + rr + 64] = pa1.w;
        Bs[(k4 * 4 + 0) * 128 + rr] = pb0.x;
        Bs[(k4 * 4 + 1) * 128 + rr] = pb0.y;
        Bs[(k4 * 4 + 2) * 128 + rr] = pb0.z;
        Bs[(k4 * 4 + 3) * 128 + rr] = pb0.w;
        Bs[(k4 * 4 + 0) * 128 + rr + 64] = pb1.x;
        Bs[(k4 * 4 + 1) * 128 + rr + 64] = pb1.y;
        Bs[(k4 * 4 + 2) * 128 + rr + 64] = pb1.z;
        Bs[(k4 * 4 + 3) * 128 + rr + 64] = pb1.w;
        __syncthreads();

        if (kt < 3) {
            const int off = (kt + 1) * 16;
            pa0 = *(const float4*)(Abase + off);
            pa1 = *(const float4*)(Abase + 64 * 64 + off);
            pb0 = *(const float4*)(Bbase + off);
            pb1 = *(const float4*)(Bbase + 64 * 64 + off);
        }

#pragma unroll
        for (int k = 0; k < 16; ++k) {
            const float4 a0 = *(const float4*)(As + k * 128 + ty * 4);
            const float4 a1 = *(const float4*)(As + k * 128 + 64 + ty * 4);
            const ulonglong2 bpa = *(const ulonglong2*)(Bs + k * 128 + tx * 4);
            const ulonglong2 bpb = *(const ulonglong2*)(Bs + k * 128 + 64 + tx * 4);
            ull ad[8];
            ad[0] = pk2(a0.x, a0.x); ad[1] = pk2(a0.y, a0.y);
            ad[2] = pk2(a0.z, a0.z); ad[3] = pk2(a0.w, a0.w);
            ad[4] = pk2(a1.x, a1.x); ad[5] = pk2(a1.y, a1.y);
            ad[6] = pk2(a1.z, a1.z); ad[7] = pk2(a1.w, a1.w);
            const ull bp[4] = {bpa.x, bpa.y, bpb.x, bpb.y};
#pragma unroll
            for (int ii = 0; ii < 8; ++ii)
#pragma unroll
                for (int jj = 0; jj < 4; ++jj)
                    acc[ii][jj] = fma2(ad[ii], bp[jj], acc[ii][jj]);
        }
        __syncthreads();
    }
    // Epilogue: scale by 1/sqrt(64) and write scores
    float* Sbase = g_S + (size_t)h * 4194304;
#pragma unroll
    for (int jh = 0; jh < 2; ++jh) {
        const int col = bn * 128 + jh * 64 + tx * 4;
#pragma unroll
        for (int ii = 0; ii < 8; ++ii) {
            const int row = bm * 128 + ((ii < 4) ? (ty * 4 + ii) : (64 + ty * 4 + ii - 4));
            const float2 c01 = upk(acc[ii][jh * 2 + 0]);
            const float2 c23 = upk(acc[ii][jh * 2 + 1]);
            float4 o;
            o.x = c01.x * 0.125f;
            o.y = c01.y * 0.125f;
            o.z = c23.x * 0.125f;
            o.w = c23.y * 0.125f;
            *(float4*)(Sbase + (size_t)row * 2048 + col) = o;
        }
    }
}

// ---------------------------------------------------------------------------
// Select + softmax: one 256-thread block per score row (32768 blocks/pass).
// Row cached in registers (8 floats/thread). Exact block-level radix select
// of the rank-T_SEL key, then masked exp, block sum, write normalized weights.
// ---------------------------------------------------------------------------
__global__ __launch_bounds__(256)
void sel_kernel()
{
    __shared__ unsigned hist[256];
    __shared__ unsigned s_pfx, s_T, s_km;
    __shared__ float    f_red[8];
    __shared__ unsigned u_red[8];
    __shared__ float    s_inv;

    const int tid = threadIdx.x, lane = tid & 31, wid = tid >> 5;
    float* srow = g_S + (size_t)blockIdx.x * 2048;

    float v[8];
    unsigned key[8];
    {
        const float4 f0 = *(const float4*)(srow + tid * 8);
        const float4 f1 = *(const float4*)(srow + tid * 8 + 4);
        v[0] = f0.x; v[1] = f0.y; v[2] = f0.z; v[3] = f0.w;
        v[4] = f1.x; v[5] = f1.y; v[6] = f1.z; v[7] = f1.w;
#pragma unroll
        for (int i = 0; i < 8; ++i) key[i] = f2key(v[i]);
    }

    // block max of keys
    {
        unsigned km = key[0];
#pragma unroll
        for (int i = 1; i < 8; ++i) km = (key[i] > km) ? key[i] : km;
#pragma unroll
        for (int o = 16; o > 0; o >>= 1) {
            const unsigned t = __shfl_xor_sync(0xffffffffu, km, o);
            km = (t > km) ? t : km;
        }
        if (lane == 0) u_red[wid] = km;
        __syncthreads();
        if (tid == 0) {
            unsigned m = u_red[0];
#pragma unroll
            for (int i = 1; i < 8; ++i) m = (u_red[i] > m) ? u_red[i] : m;
            s_km = m;
        }
    }

    // 4-pass MSB-first byte radix select for ascending rank T_SEL
    unsigned prefix = 0, T = T_SEL;
#pragma unroll
    for (int b = 3; b >= 0; --b) {
        hist[tid] = 0;
        __syncthreads();
        const unsigned himask = (b == 3) ? 0u : (0xFFFFFFFFu << ((b + 1) * 8));
#pragma unroll
        for (int i = 0; i < 8; ++i) {
            const bool act = ((key[i] & himask) == prefix);
            const unsigned bin = (key[i] >> (b * 8)) & 255;
            const unsigned tag = act ? bin : (0x100u + (unsigned)lane);
            const unsigned grp = __match_any_sync(0xffffffffu, tag);
            if (act && lane == (__ffs(grp) - 1))
                atomicAdd(&hist[bin], (unsigned)__popc(grp));
        }
        __syncthreads();
        if (wid == 0) {
            unsigned c[8], lsum = 0;
#pragma unroll
            for (int i = 0; i < 8; ++i) { c[i] = hist[lane * 8 + i]; lsum += c[i]; }
            unsigned inc = lsum;
#pragma unroll
            for (int o = 1; o < 32; o <<= 1) {
                const unsigned t = __shfl_up_sync(0xffffffffu, inc, o);
                if (lane >= o) inc += t;
            }
            const unsigned exl = inc - lsum;
            if (T >= exl && T < exl + lsum) {   // exactly one lane owns
                unsigned cum = exl;
#pragma unroll
                for (int i = 0; i < 8; ++i) {
                    if (T < cum + c[i]) {
                        s_pfx = prefix | ((unsigned)(lane * 8 + i) << (b * 8));
                        s_T   = T - cum;
                        break;
                    }
                    cum += c[i];
                }
            }
        }
        __syncthreads();
        prefix = s_pfx;
        T = s_T;
        __syncthreads();
    }

    // masked exp + block sum
    const unsigned tk = prefix;
    const float m = key2f(s_km);
    float w[8];
    float lsum = 0.0f;
#pragma unroll
    for (int i = 0; i < 8; ++i) {
        w[i] = (key[i] >= tk) ? fexp(v[i] - m) : 0.0f;
        lsum += w[i];
    }
#pragma unroll
    for (int o = 16; o > 0; o >>= 1)
        lsum += __shfl_xor_sync(0xffffffffu, lsum, o);
    if (lane == 0) f_red[wid] = lsum;
    __syncthreads();
    if (tid == 0) {
        float t = 0.0f;
#pragma unroll
        for (int i = 0; i < 8; ++i) t += f_red[i];
        s_inv = 1.0f / t;
    }
    __syncthreads();
    const float inv = s_inv;

    float4 o0 = make_float4(w[0] * inv, w[1] * inv, w[2] * inv, w[3] * inv);
    float4 o1 = make_float4(w[4] * inv, w[5] * inv, w[6] * inv, w[7] * inv);
    *(float4*)(srow + tid * 8)     = o0;
    *(float4*)(srow + tid * 8 + 4) = o1;
}

// ---------------------------------------------------------------------------
// PV for one n: per-h GEMM  O[2048,64] = W[2048,2048] @ V[2048,64]
// BM=64, BN=64 (full d), BK=128, 256 threads, 4l x 4d micro via FFMA2.
// W tile stored TRANSPOSED in smem (Wt[s][l], stride 65); the 4 scalar W
// reads per s are warp-broadcast (address depends only on ty).
// smem 64.5KB -> 3 blocks/SM; grid 32x16 = 512 blocks/pass.
// Output scattered to g_O[(l,n)][d*16+h] for the O projection.
// ---------------------------------------------------------------------------
#define PV_LSTR 65
#define PV_SMEM_BYTES ((128 * PV_LSTR + 128 * 64) * 4)

__global__ __launch_bounds__(256, 3)
void pv_kernel(int n)
{
    extern __shared__ float psm[];
    float* Wt = psm;                 // [128 s][PV_LSTR l] (transposed)
    float* Vs = psm + 128 * PV_LSTR; // [128 s][64 d]

    const int tid = threadIdx.x;
    const int h = blockIdx.y, bm = blockIdx.x;
    const int nh = n * 16 + h;
    const int ty = tid >> 4, tx = tid & 15;   // ty: l quad (0..15), tx: d quad

    const float* Wrow  = g_S + (size_t)h * 4194304 + (size_t)bm * 64 * 2048;
    const float* Vbase = g_Vp + (size_t)nh * 131072;

    ull acc[2][4];
#pragma unroll
    for (int i = 0; i < 2; ++i)
#pragma unroll
        for (int j = 0; j < 4; ++j) acc[i][j] = 0ull;

    for (int kt = 0; kt < 16; ++kt) {
        // W tile [64 l][128 s] from GMEM -> transposed Wt[s][l] in smem
#pragma unroll
        for (int i = 0; i < 8; ++i) {
            const int idx = i * 256 + tid;
            const int lr = idx >> 5, sq = idx & 31;
            const float4 w = *(const float4*)(Wrow + (size_t)lr * 2048 + kt * 128 + sq * 4);
            Wt[(sq * 4 + 0) * PV_LSTR + lr] = w.x;
            Wt[(sq * 4 + 1) * PV_LSTR + lr] = w.y;
            Wt[(sq * 4 + 2) * PV_LSTR + lr] = w.z;
            Wt[(sq * 4 + 3) * PV_LSTR + lr] = w.w;
        }
        // V tile [128 s][64 d]
#pragma unroll
        for (int i = 0; i < 8; ++i) {
            const int idx = i * 256 + tid;
            const int sr = idx >> 4, d4 = idx & 15;
            *(float4*)(Vs + sr * 64 + d4 * 4) =
                *(const float4*)(Vbase + (size_t)(kt * 128 + sr) * 64 + d4 * 4);
        }
        __syncthreads();

        const float* wb = Wt + ty * 4;
        const float* vb = Vs + tx * 4;
#pragma unroll 4
        for (int s = 0; s < 128; ++s) {
            const float* wr = wb + s * PV_LSTR;   // W[l = ty*4 .. ty*4+3][s]
            const ull p0 = pk2(wr[0], wr[1]);
            const ull p1 = pk2(wr[2], wr[3]);
            const float4 vv = *(const float4*)(vb + s * 64);
            const ull v0 = pk2(vv.x, vv.x);
            const ull v1 = pk2(vv.y, vv.y);
            const ull v2 = pk2(vv.z, vv.z);
            const ull v3 = pk2(vv.w, vv.w);
            acc[0][0] = fma2(p0, v0, acc[0][0]);
            acc[0][1] = fma2(p0, v1, acc[0][1]);
            acc[0][2] = fma2(p0, v2, acc[0][2]);
            acc[0][3] = fma2(p0, v3, acc[0][3]);
            acc[1][0] = fma2(p1, v0, acc[1][0]);
            acc[1][1] = fma2(p1, v1, acc[1][1]);
            acc[1][2] = fma2(p1, v2, acc[1][2]);
            acc[1][3] = fma2(p1, v3, acc[1][3]);
        }
        __syncthreads();
    }

    // Epilogue: scatter to g_O[(l,n)][d*16+h]
#pragma unroll
    for (int lp = 0; lp < 2; ++lp) {
        const int l0 = bm * 64 + ty * 4 + lp * 2;
        float* o0 = g_O + (size_t)(l0 * 2 + n) * 1024 + h;
        float* o1 = g_O + (size_t)((l0 + 1) * 2 + n) * 1024 + h;
#pragma unroll
        for (int j = 0; j < 4; ++j) {
            const float2 r = upk(acc[lp][j]);
            const int d = tx * 4 + j;
            o0[d * 16] = r.x;
            o1[d * 16] = r.y;
        }
    }
}

// ---------------------------------------------------------------------------
// Launch
// ---------------------------------------------------------------------------
extern "C" void kernel_launch(void* const* d_in, const int* in_sizes, int n_in,
                              void* d_out, int out_size)
{
    (void)in_sizes; (void)n_in; (void)out_size;
    const float* query = (const float*)d_in[0];
    const float* key   = (const float*)d_in[1];
    const float* value = (const float*)d_in[2];
    const float* Wq = (const float*)d_in[3];
    const float* bq = (const float*)d_in[4];
    const float* Wk = (const float*)d_in[5];
    const float* bk = (const float*)d_in[6];
    const float* Wv = (const float*)d_in[7];
    const float* bv = (const float*)d_in[8];
    const float* Wo = (const float*)d_in[9];
    const float* bo = (const float*)d_in[10];

    float *Qp, *Kp, *Vp, *O;
    cudaGetSymbolAddress((void**)&Qp, g_Qp);
    cudaGetSymbolAddress((void**)&Kp, g_Kp);
    cudaGetSymbolAddress((void**)&Vp, g_Vp);
    cudaGetSymbolAddress((void**)&O,  g_O);

    cudaFuncSetAttribute(pv_kernel, cudaFuncAttributeMaxDynamicSharedMemorySize,
                         PV_SMEM_BYTES);

    gemm_qkv_kernel<<<dim3(8, 32, 3), 256>>>(query, key, value,
                                             Wq, bq, Wk, bk, Wv, bv,
                                             Qp, Kp, Vp);

    for (int n = 0; n < N_B; ++n) {
        qk_kernel<<<dim3(16, 16, 16), 256>>>(n);
        sel_kernel<<<32768, 256>>>();
        pv_kernel<<<dim3(32, 16), 256, PV_SMEM_BYTES>>>(n);
    }

    gemm_o_kernel<<<dim3(8, 32), 256>>>(O, Wo, bo, (float*)d_out);
}

// round 15
// speedup vs baseline: 2.3783x; 1.6577x over previous
#include <cuda_runtime.h>
#include <cstdint>

typedef unsigned long long ull;

// Problem constants
#define L_DIM   2048
#define N_B     2
#define E_DIM   1024
#define H_N     16
#define D_H     64
#define S_DIM   2048
#define K_SEL   1176              // int(2048 * sigmoid(0.3))
#define T_SEL   (S_DIM - K_SEL)   // 872: 0-based ascending rank of threshold

// Scratch (static device arrays are allowed; cudaMalloc is not)
__device__ float g_Qp[4096 * 1024];     // [n][h][l][d]
__device__ float g_Kp[4096 * 1024];     // [n][h][l][d]
__device__ float g_Vp[4096 * 1024];     // [n][h][l][d]
__device__ float g_O [4096 * 1024];     // [(l,n)][d*16+h]
__device__ float g_S [67108864];        // [h][l][s] scores for ONE n (256 MB)

// ---------------------------------------------------------------------------
// Helpers
// ---------------------------------------------------------------------------
__device__ __forceinline__ unsigned f2key(float f) {
    unsigned u = __float_as_uint(f);
    return (u & 0x80000000u) ? ~u : (u | 0x80000000u);
}
__device__ __forceinline__ float key2f(unsigned k) {
    unsigned u = (k & 0x80000000u) ? (k ^ 0x80000000u) : ~k;
    return __uint_as_float(u);
}
// Fast e^x for x <= 0 (poly exp2, ~1e-7 rel err). Avoids MUFU bottleneck.
__device__ __forceinline__ float fexp(float x) {
    float y = x * 1.4426950408889634f;
    y = fmaxf(y, -120.0f);
    float fl = floorf(y);
    float f  = y - fl;
    float p  =             1.53533619e-4f;
    p = fmaf(p, f, 1.33988744e-3f);
    p = fmaf(p, f, 9.61843736e-3f);
    p = fmaf(p, f, 5.55033247e-2f);
    p = fmaf(p, f, 2.40226479e-1f);
    p = fmaf(p, f, 6.93147203e-1f);
    p = fmaf(p, f, 1.0f);
    return p * __int_as_float(((int)fl + 127) << 23);
}

// --- packed f32x2 ops (Blackwell, sm_100+) ---
__device__ __forceinline__ ull pk2(float a, float b) {
    ull r;
    asm("mov.b64 %0, {%1, %2};" : "=l"(r) : "r"(__float_as_uint(a)), "r"(__float_as_uint(b)));
    return r;
}
__device__ __forceinline__ ull fma2(ull a, ull b, ull c) {
    ull d;
    asm("fma.rn.f32x2 %0, %1, %2, %3;" : "=l"(d) : "l"(a), "l"(b), "l"(c));
    return d;
}
__device__ __forceinline__ float2 upk(ull v) {
    unsigned lo, hi;
    asm("mov.b64 {%0, %1}, %2;" : "=r"(lo), "=r"(hi) : "l"(v));
    return make_float2(__uint_as_float(lo), __uint_as_float(hi));
}

// ---------------------------------------------------------------------------
// Projection GEMM: C = A[4096,1024] @ W^T + bias. SCATTER=true writes the
// result into [n][h][l][d] layout; false writes row-major (final output).
// BM=BN=128, BK=16, 256 threads, 8x8 micro via 32 FFMA2, reg prefetch.
// ---------------------------------------------------------------------------
template <bool SCATTER>
__device__ __forceinline__
void gemm_body(const float* __restrict__ A, const float* __restrict__ B,
               const float* __restrict__ bias, float* __restrict__ C,
               int bm, int bn)
{
    __shared__ float As[16 * 128];
    __shared__ float Bs[16 * 128];
    const int tid = threadIdx.x;
    const int ty = tid >> 4, tx = tid & 15;
    const int rr = tid >> 2, k4 = tid & 3;

    ull acc[8][4];
#pragma unroll
    for (int i = 0; i < 8; ++i)
#pragma unroll
        for (int j = 0; j < 4; ++j) acc[i][j] = 0ull;

    const float* Abase = A + (size_t)(bm * 128 + rr) * 1024 + k4 * 4;
    const float* Bbase = B + (size_t)(bn * 128 + rr) * 1024 + k4 * 4;

    float4 pa0 = *(const float4*)(Abase);
    float4 pa1 = *(const float4*)(Abase + (size_t)64 * 1024);
    float4 pb0 = *(const float4*)(Bbase);
    float4 pb1 = *(const float4*)(Bbase + (size_t)64 * 1024);

    for (int kt = 0; kt < 64; ++kt) {
        As[(k4 * 4 + 0) * 128 + rr] = pa0.x;
        As[(k4 * 4 + 1) * 128 + rr] = pa0.y;
        As[(k4 * 4 + 2) * 128 + rr] = pa0.z;
        As[(k4 * 4 + 3) * 128 + rr] = pa0.w;
        As[(k4 * 4 + 0) * 128 + rr + 64] = pa1.x;
        As[(k4 * 4 + 1) * 128 + rr + 64] = pa1.y;
        As[(k4 * 4 + 2) * 128 + rr + 64] = pa1.z;
        As[(k4 * 4 + 3) * 128 + rr + 64] = pa1.w;
        Bs[(k4 * 4 + 0) * 128 + rr] = pb0.x;
        Bs[(k4 * 4 + 1) * 128 + rr] = pb0.y;
        Bs[(k4 * 4 + 2) * 128 + rr] = pb0.z;
        Bs[(k4 * 4 + 3) * 128 + rr] = pb0.w;
        Bs[(k4 * 4 + 0) * 128 + rr + 64] = pb1.x;
        Bs[(k4 * 4 + 1) * 128 + rr + 64] = pb1.y;
        Bs[(k4 * 4 + 2) * 128 + rr + 64] = pb1.z;
        Bs[(k4 * 4 + 3) * 128 + rr + 64] = pb1.w;
        __syncthreads();

        if (kt < 63) {
            const int off = (kt + 1) * 16;
            pa0 = *(const float4*)(Abase + off);
            pa1 = *(const float4*)(Abase + (size_t)64 * 1024 + off);
            pb0 = *(const float4*)(Bbase + off);
            pb1 = *(const float4*)(Bbase + (size_t)64 * 1024 + off);
        }

#pragma unroll
        for (int k = 0; k < 16; ++k) {
            const float4 a0 = *(const float4*)(As + k * 128 + ty * 4);
            const float4 a1 = *(const float4*)(As + k * 128 + 64 + ty * 4);
            const ulonglong2 bpa = *(const ulonglong2*)(Bs + k * 128 + tx * 4);
            const ulonglong2 bpb = *(const ulonglong2*)(Bs + k * 128 + 64 + tx * 4);
            ull ad[8];
            ad[0] = pk2(a0.x, a0.x); ad[1] = pk2(a0.y, a0.y);
            ad[2] = pk2(a0.z, a0.z); ad[3] = pk2(a0.w, a0.w);
            ad[4] = pk2(a1.x, a1.x); ad[5] = pk2(a1.y, a1.y);
            ad[6] = pk2(a1.z, a1.z); ad[7] = pk2(a1.w, a1.w);
            const ull bp[4] = {bpa.x, bpa.y, bpb.x, bpb.y};
#pragma unroll
            for (int ii = 0; ii < 8; ++ii)
#pragma unroll
                for (int jj = 0; jj < 4; ++jj)
                    acc[ii][jj] = fma2(ad[ii], bp[jj], acc[ii][jj]);
        }
        __syncthreads();
    }
    // Epilogue with bias
#pragma unroll
    for (int jh = 0; jh < 2; ++jh) {
        const int col = bn * 128 + jh * 64 + tx * 4;
        const float4 bb = *(const float4*)(bias + col);
#pragma unroll
        for (int ii = 0; ii < 8; ++ii) {
            const int row = bm * 128 + ((ii < 4) ? (ty * 4 + ii) : (64 + ty * 4 + ii - 4));
            const float2 c01 = upk(acc[ii][jh * 2 + 0]);
            const float2 c23 = upk(acc[ii][jh * 2 + 1]);
            float4 o;
            o.x = c01.x + bb.x;
            o.y = c01.y + bb.y;
            o.z = c23.x + bb.z;
            o.w = c23.y + bb.w;
            if (SCATTER) {
                // row=(l,n), col=(h,d) -> [n][h][l][d]
                const int l = row >> 1, nn = row & 1;
                const int h = bn * 2 + jh, d = tx * 4;
                *(float4*)(C + ((size_t)(nn * 16 + h) * 2048 + l) * 64 + d) = o;
            } else {
                *(float4*)(C + (size_t)row * 1024 + col) = o;
            }
        }
    }
}

__global__ __launch_bounds__(256, 2)
void gemm_qkv_kernel(const float* __restrict__ q, const float* __restrict__ k,
                     const float* __restrict__ v,
                     const float* __restrict__ Wq, const float* __restrict__ bq,
                     const float* __restrict__ Wk, const float* __restrict__ bk,
                     const float* __restrict__ Wv, const float* __restrict__ bv,
                     float* __restrict__ Qp, float* __restrict__ Kp, float* __restrict__ Vp)
{
    const int which = blockIdx.z;
    const float* A    = (which == 0) ? q  : (which == 1) ? k  : v;
    const float* B    = (which == 0) ? Wq : (which == 1) ? Wk : Wv;
    const float* bias = (which == 0) ? bq : (which == 1) ? bk : bv;
    float*       C    = (which == 0) ? Qp : (which == 1) ? Kp : Vp;
    gemm_body<true>(A, B, bias, C, blockIdx.y, blockIdx.x);
}

__global__ __launch_bounds__(256, 2)
void gemm_o_kernel(const float* __restrict__ A, const float* __restrict__ B,
                   const float* __restrict__ bias, float* __restrict__ C)
{
    gemm_body<false>(A, B, bias, C, blockIdx.y, blockIdx.x);
}

// ---------------------------------------------------------------------------
// QK^T for one n: per-h GEMM  S[2048,2048] = Q[2048,64] @ K^T * 0.125
// BM=BN=128, BK=16 x4, 256 threads, same micro-tiling as gemm_body.
// ---------------------------------------------------------------------------
__global__ __launch_bounds__(256, 2)
void qk_kernel(int n)
{
    __shared__ float As[16 * 128];
    __shared__ float Bs[16 * 128];
    const int tid = threadIdx.x;
    const int h = blockIdx.z, bm = blockIdx.y, bn = blockIdx.x;
    const int nh = n * 16 + h;
    const int ty = tid >> 4, tx = tid & 15;
    const int rr = tid >> 2, k4 = tid & 3;

    const float* A = g_Qp + (size_t)nh * 131072;  // 2048*64
    const float* B = g_Kp + (size_t)nh * 131072;

    ull acc[8][4];
#pragma unroll
    for (int i = 0; i < 8; ++i)
#pragma unroll
        for (int j = 0; j < 4; ++j) acc[i][j] = 0ull;

    const float* Abase = A + (size_t)(bm * 128 + rr) * 64 + k4 * 4;
    const float* Bbase = B + (size_t)(bn * 128 + rr) * 64 + k4 * 4;

    float4 pa0 = *(const float4*)(Abase);
    float4 pa1 = *(const float4*)(Abase + 64 * 64);
    float4 pb0 = *(const float4*)(Bbase);
    float4 pb1 = *(const float4*)(Bbase + 64 * 64);

#pragma unroll
    for (int kt = 0; kt < 4; ++kt) {
        As[(k4 * 4 + 0) * 128 + rr] = pa0.x;
        As[(k4 * 4 + 1) * 128 + rr] = pa0.y;
        As[(k4 * 4 + 2) * 128 + rr] = pa0.z;
        As[(k4 * 4 + 3) * 128 + rr] = pa0.w;
        As[(k4 * 4 + 0) * 128 + rr + 64] = pa1.x;
        As[(k4 * 4 + 1) * 128 + rr + 64] = pa1.y;
        As[(k4 * 4 + 2) * 128 + rr + 64] = pa1.z;
        As[(k4 * 4 + 3) * 128 + rr + 64] = pa1.w;
        Bs[(k4 * 4 + 0) * 128 + rr] = pb0.x;
        Bs[(k4 * 4 + 1) * 128 + rr] = pb0.y;
        Bs[(k4 * 4 + 2) * 128 + rr] = pb0.z;
        Bs[(k4 * 4 + 3) * 128 + rr] = pb0.w;
        Bs[(k4 * 4 + 0) * 128 + rr + 64] = pb1.x;
        Bs[(k4 * 4 + 1) * 128 + rr + 64] = pb1.y;
        Bs[(k4 * 4 + 2) * 128 + rr + 64] = pb1.z;
        Bs[(k4 * 4 + 3) * 128 + rr + 64] = pb1.w;
        __syncthreads();

        if (kt < 3) {
            const int off = (kt + 1) * 16;
            pa0 = *(const float4*)(Abase + off);
            pa1 = *(const float4*)(Abase + 64 * 64 + off);
            pb0 = *(const float4*)(Bbase + off);
            pb1 = *(const float4*)(Bbase + 64 * 64 + off);
        }

#pragma unroll
        for (int k = 0; k < 16; ++k) {
            const float4 a0 = *(const float4*)(As + k * 128 + ty * 4);
            const float4 a1 = *(const float4*)(As + k * 128 + 64 + ty * 4);
            const ulonglong2 bpa = *(const ulonglong2*)(Bs + k * 128 + tx * 4);
            const ulonglong2 bpb = *(const ulonglong2*)(Bs + k * 128 + 64 + tx * 4);
            ull ad[8];
            ad[0] = pk2(a0.x, a0.x); ad[1] = pk2(a0.y, a0.y);
            ad[2] = pk2(a0.z, a0.z); ad[3] = pk2(a0.w, a0.w);
            ad[4] = pk2(a1.x, a1.x); ad[5] = pk2(a1.y, a1.y);
            ad[6] = pk2(a1.z, a1.z); ad[7] = pk2(a1.w, a1.w);
            const ull bp[4] = {bpa.x, bpa.y, bpb.x, bpb.y};
#pragma unroll
            for (int ii = 0; ii < 8; ++ii)
#pragma unroll
                for (int jj = 0; jj < 4; ++jj)
                    acc[ii][jj] = fma2(ad[ii], bp[jj], acc[ii][jj]);
        }
        __syncthreads();
    }
    // Epilogue: scale by 1/sqrt(64) and write scores
    float* Sbase = g_S + (size_t)h * 4194304;
#pragma unroll
    for (int jh = 0; jh < 2; ++jh) {
        const int col = bn * 128 + jh * 64 + tx * 4;
#pragma unroll
        for (int ii = 0; ii < 8; ++ii) {
            const int row = bm * 128 + ((ii < 4) ? (ty * 4 + ii) : (64 + ty * 4 + ii - 4));
            const float2 c01 = upk(acc[ii][jh * 2 + 0]);
            const float2 c23 = upk(acc[ii][jh * 2 + 1]);
            float4 o;
            o.x = c01.x * 0.125f;
            o.y = c01.y * 0.125f;
            o.z = c23.x * 0.125f;
            o.w = c23.y * 0.125f;
            *(float4*)(Sbase + (size_t)row * 2048 + col) = o;
        }
    }
}

// ---------------------------------------------------------------------------
// Select + softmax: one 256-thread block per score row (32768 blocks/pass).
// Row cached in registers. Pass b=3 uses warp-aggregated atomics (exponent
// byte -> heavy bin conflicts); passes b=2..0 use plain predicated atomics
// (few active keys, near-uniform bins) -- no match_any cost.
// ---------------------------------------------------------------------------
__global__ __launch_bounds__(256)
void sel_kernel()
{
    __shared__ unsigned hist[256];
    __shared__ unsigned s_pfx, s_T, s_km;
    __shared__ float    f_red[8];
    __shared__ unsigned u_red[8];
    __shared__ float    s_inv;

    const int tid = threadIdx.x, lane = tid & 31, wid = tid >> 5;
    float* srow = g_S + (size_t)blockIdx.x * 2048;

    float v[8];
    unsigned key[8];
    {
        const float4 f0 = *(const float4*)(srow + tid * 8);
        const float4 f1 = *(const float4*)(srow + tid * 8 + 4);
        v[0] = f0.x; v[1] = f0.y; v[2] = f0.z; v[3] = f0.w;
        v[4] = f1.x; v[5] = f1.y; v[6] = f1.z; v[7] = f1.w;
#pragma unroll
        for (int i = 0; i < 8; ++i) key[i] = f2key(v[i]);
    }

    // block max of keys
    {
        unsigned km = key[0];
#pragma unroll
        for (int i = 1; i < 8; ++i) km = (key[i] > km) ? key[i] : km;
#pragma unroll
        for (int o = 16; o > 0; o >>= 1) {
            const unsigned t = __shfl_xor_sync(0xffffffffu, km, o);
            km = (t > km) ? t : km;
        }
        if (lane == 0) u_red[wid] = km;
        __syncthreads();
        if (tid == 0) {
            unsigned m = u_red[0];
#pragma unroll
            for (int i = 1; i < 8; ++i) m = (u_red[i] > m) ? u_red[i] : m;
            s_km = m;
        }
    }

    unsigned prefix = 0, T = T_SEL;

    // ---- pass b=3: all 2048 keys; warp-aggregated (few distinct exp bins) ----
    {
        hist[tid] = 0;
        __syncthreads();
#pragma unroll
        for (int i = 0; i < 8; ++i) {
            const unsigned bin = key[i] >> 24;
            const unsigned grp = __match_any_sync(0xffffffffu, bin);
            if (lane == (__ffs(grp) - 1))
                atomicAdd(&hist[bin], (unsigned)__popc(grp));
        }
        __syncthreads();
        if (wid == 0) {
            unsigned c[8], lsum = 0;
#pragma unroll
            for (int i = 0; i < 8; ++i) { c[i] = hist[lane * 8 + i]; lsum += c[i]; }
            unsigned inc = lsum;
#pragma unroll
            for (int o = 1; o < 32; o <<= 1) {
                const unsigned t = __shfl_up_sync(0xffffffffu, inc, o);
                if (lane >= o) inc += t;
            }
            const unsigned exl = inc - lsum;
            if (T >= exl && T < exl + lsum) {
                unsigned cum = exl;
#pragma unroll
                for (int i = 0; i < 8; ++i) {
                    if (T < cum + c[i]) {
                        s_pfx = (unsigned)(lane * 8 + i) << 24;
                        s_T   = T - cum;
                        break;
                    }
                    cum += c[i];
                }
            }
        }
        __syncthreads();
        prefix = s_pfx;
        T = s_T;
        __syncthreads();
    }

    // ---- passes b=2..0: only prefix-matching keys; plain atomics ----
#pragma unroll
    for (int b = 2; b >= 0; --b) {
        hist[tid] = 0;
        __syncthreads();
        const unsigned himask = 0xFFFFFFFFu << ((b + 1) * 8);
#pragma unroll
        for (int i = 0; i < 8; ++i) {
            if ((key[i] & himask) == prefix)
                atomicAdd(&hist[(key[i] >> (b * 8)) & 255], 1u);
        }
        __syncthreads();
        if (wid == 0) {
            unsigned c[8], lsum = 0;
#pragma unroll
            for (int i = 0; i < 8; ++i) { c[i] = hist[lane * 8 + i]; lsum += c[i]; }
            unsigned inc = lsum;
#pragma unroll
            for (int o = 1; o < 32; o <<= 1) {
                const unsigned t = __shfl_up_sync(0xffffffffu, inc, o);
                if (lane >= o) inc += t;
            }
            const unsigned exl = inc - lsum;
            if (T >= exl && T < exl + lsum) {
                unsigned cum = exl;
#pragma unroll
                for (int i = 0; i < 8; ++i) {
                    if (T < cum + c[i]) {
                        s_pfx = prefix | ((unsigned)(lane * 8 + i) << (b * 8));
                        s_T   = T - cum;
                        break;
                    }
                    cum += c[i];
                }
            }
        }
        __syncthreads();
        prefix = s_pfx;
        T = s_T;
        __syncthreads();
    }

    // masked exp + block sum
    const unsigned tk = prefix;
    const float m = key2f(s_km);
    float w[8];
    float lsum = 0.0f;
#pragma unroll
    for (int i = 0; i < 8; ++i) {
        w[i] = (key[i] >= tk) ? fexp(v[i] - m) : 0.0f;
        lsum += w[i];
    }
#pragma unroll
    for (int o = 16; o > 0; o >>= 1)
        lsum += __shfl_xor_sync(0xffffffffu, lsum, o);
    if (lane == 0) f_red[wid] = lsum;
    __syncthreads();
    if (tid == 0) {
        float t = 0.0f;
#pragma unroll
        for (int i = 0; i < 8; ++i) t += f_red[i];
        s_inv = 1.0f / t;
    }
    __syncthreads();
    const float inv = s_inv;

    float4 o0 = make_float4(w[0] * inv, w[1] * inv, w[2] * inv, w[3] * inv);
    float4 o1 = make_float4(w[4] * inv, w[5] * inv, w[6] * inv, w[7] * inv);
    *(float4*)(srow + tid * 8)     = o0;
    *(float4*)(srow + tid * 8 + 4) = o1;
}

// ---------------------------------------------------------------------------
// PV for one n: per-h GEMM  O[2048,64] = W[2048,2048] @ V[2048,64]
// BM=64, BK=128, 256 threads, 2l x 8d micro: natural V d-pairs, dup'd W.
// Wt transposed (stride 65); W reads warp-broadcast. 3 blocks/SM; grid 32x16.
// ---------------------------------------------------------------------------
#define PV_LSTR 65
#define PV_SMEM_BYTES ((128 * PV_LSTR + 128 * 64) * 4)

__global__ __launch_bounds__(256, 3)
void pv_kernel(int n)
{
    extern __shared__ float psm[];
    float* Wt = psm;                 // [128 s][PV_LSTR l] (transposed)
    float* Vs = psm + 128 * PV_LSTR; // [128 s][64 d]

    const int tid = threadIdx.x;
    const int h = blockIdx.y, bm = blockIdx.x;
    const int nh = n * 16 + h;
    const int ty = tid >> 3, tx = tid & 7;    // ty: l pair (0..31), tx: d octet

    const float* Wrow  = g_S + (size_t)h * 4194304 + (size_t)bm * 64 * 2048;
    const float* Vbase = g_Vp + (size_t)nh * 131072;

    ull acc[2][4];
#pragma unroll
    for (int i = 0; i < 2; ++i)
#pragma unroll
        for (int j = 0; j < 4; ++j) acc[i][j] = 0ull;

    for (int kt = 0; kt < 16; ++kt) {
        // W tile [64 l][128 s] -> transposed Wt[s][l]
#pragma unroll
        for (int i = 0; i < 8; ++i) {
            const int idx = i * 256 + tid;
            const int lr = idx >> 5, sq = idx & 31;
            const float4 w = *(const float4*)(Wrow + (size_t)lr * 2048 + kt * 128 + sq * 4);
            Wt[(sq * 4 + 0) * PV_LSTR + lr] = w.x;
            Wt[(sq * 4 + 1) * PV_LSTR + lr] = w.y;
            Wt[(sq * 4 + 2) * PV_LSTR + lr] = w.z;
            Wt[(sq * 4 + 3) * PV_LSTR + lr] = w.w;
        }
        // V tile [128 s][64 d]
#pragma unroll
        for (int i = 0; i < 8; ++i) {
            const int idx = i * 256 + tid;
            const int sr = idx >> 4, d4 = idx & 15;
            *(float4*)(Vs + sr * 64 + d4 * 4) =
                *(const float4*)(Vbase + (size_t)(kt * 128 + sr) * 64 + d4 * 4);
        }
        __syncthreads();

        const float* wb = Wt + ty * 2;
        const float* vb = Vs + tx * 8;
#pragma unroll 4
        for (int s = 0; s < 128; ++s) {
            const float* wr = wb + s * PV_LSTR;       // W[l=2ty, 2ty+1][s]
            const ull wd0 = pk2(wr[0], wr[0]);
            const ull wd1 = pk2(wr[1], wr[1]);
            const ulonglong2 va = *(const ulonglong2*)(vb + s * 64);       // d pairs 0..1
            const ulonglong2 vc = *(const ulonglong2*)(vb + s * 64 + 4);   // d pairs 2..3
            acc[0][0] = fma2(wd0, va.x, acc[0][0]);
            acc[0][1] = fma2(wd0, va.y, acc[0][1]);
            acc[0][2] = fma2(wd0, vc.x, acc[0][2]);
            acc[0][3] = fma2(wd0, vc.y, acc[0][3]);
            acc[1][0] = fma2(wd1, va.x, acc[1][0]);
            acc[1][1] = fma2(wd1, va.y, acc[1][1]);
            acc[1][2] = fma2(wd1, vc.x, acc[1][2]);
            acc[1][3] = fma2(wd1, vc.y, acc[1][3]);
        }
        __syncthreads();
    }

    // Epilogue: scatter to g_O[(l,n)][d*16+h]
#pragma unroll
    for (int lp = 0; lp < 2; ++lp) {
        const int lg = bm * 64 + ty * 2 + lp;
        float* op = g_O + (size_t)(lg * 2 + n) * 1024 + h;
#pragma unroll
        for (int j = 0; j < 4; ++j) {
            const float2 r = upk(acc[lp][j]);
            const int d = tx * 8 + j * 2;
            op[d * 16]       = r.x;
            op[(d + 1) * 16] = r.y;
        }
    }
}

// ---------------------------------------------------------------------------
// Launch
// ---------------------------------------------------------------------------
extern "C" void kernel_launch(void* const* d_in, const int* in_sizes, int n_in,
                              void* d_out, int out_size)
{
    (void)in_sizes; (void)n_in; (void)out_size;
    const float* query = (const float*)d_in[0];
    const float* key   = (const float*)d_in[1];
    const float* value = (const float*)d_in[2];
    const float* Wq = (const float*)d_in[3];
    const float* bq = (const float*)d_in[4];
    const float* Wk = (const float*)d_in[5];
    const float* bk = (const float*)d_in[6];
    const float* Wv = (const float*)d_in[7];
    const float* bv = (const float*)d_in[8];
    const float* Wo = (const float*)d_in[9];
    const float* bo = (const float*)d_in[10];

    float *Qp, *Kp, *Vp, *O;
    cudaGetSymbolAddress((void**)&Qp, g_Qp);
    cudaGetSymbolAddress((void**)&Kp, g_Kp);
    cudaGetSymbolAddress((void**)&Vp, g_Vp);
    cudaGetSymbolAddress((void**)&O,  g_O);

    cudaFuncSetAttribute(pv_kernel, cudaFuncAttributeMaxDynamicSharedMemorySize,
                         PV_SMEM_BYTES);

    gemm_qkv_kernel<<<dim3(8, 32, 3), 256>>>(query, key, value,
                                             Wq, bq, Wk, bk, Wv, bv,
                                             Qp, Kp, Vp);

    for (int n = 0; n < N_B; ++n) {
        qk_kernel<<<dim3(16, 16, 16), 256>>>(n);
        sel_kernel<<<32768, 256>>>();
        pv_kernel<<<dim3(32, 16), 256, PV_SMEM_BYTES>>>(n);
    }

    gemm_o_kernel<<<dim3(8, 32), 256>>>(O, Wo, bo, (float*)d_out);
}

// round 16
// speedup vs baseline: 3.0605x; 1.2868x over previous
#include <cuda_runtime.h>
#include <cstdint>

typedef unsigned long long ull;

// Problem constants
#define L_DIM   2048
#define N_B     2
#define E_DIM   1024
#define H_N     16
#define D_H     64
#define S_DIM   2048
#define K_SEL   1176              // int(2048 * sigmoid(0.3))
#define T_SEL   (S_DIM - K_SEL)   // 872: 0-based ascending rank of threshold

// Scratch (static device arrays are allowed; cudaMalloc is not)
__device__ float g_Qp[4096 * 1024];     // [n][h][l][d]
__device__ float g_Kp[4096 * 1024];     // [n][h][l][d]
__device__ float g_Vp[4096 * 1024];     // [n][h][l][d]
__device__ float g_O [4096 * 1024];     // [(l,n)][d*16+h]
__device__ float g_S [67108864];        // [h][l][s] scores for ONE n (256 MB)

// ---------------------------------------------------------------------------
// Helpers
// ---------------------------------------------------------------------------
__device__ __forceinline__ unsigned f2key(float f) {
    unsigned u = __float_as_uint(f);
    return (u & 0x80000000u) ? ~u : (u | 0x80000000u);
}
__device__ __forceinline__ float key2f(unsigned k) {
    unsigned u = (k & 0x80000000u) ? (k ^ 0x80000000u) : ~k;
    return __uint_as_float(u);
}
// Fast e^x for x <= 0 (poly exp2, ~1e-7 rel err). Avoids MUFU bottleneck.
__device__ __forceinline__ float fexp(float x) {
    float y = x * 1.4426950408889634f;
    y = fmaxf(y, -120.0f);
    float fl = floorf(y);
    float f  = y - fl;
    float p  =             1.53533619e-4f;
    p = fmaf(p, f, 1.33988744e-3f);
    p = fmaf(p, f, 9.61843736e-3f);
    p = fmaf(p, f, 5.55033247e-2f);
    p = fmaf(p, f, 2.40226479e-1f);
    p = fmaf(p, f, 6.93147203e-1f);
    p = fmaf(p, f, 1.0f);
    return p * __int_as_float(((int)fl + 127) << 23);
}

// --- packed f32x2 ops (Blackwell, sm_100+) ---
__device__ __forceinline__ ull pk2(float a, float b) {
    ull r;
    asm("mov.b64 %0, {%1, %2};" : "=l"(r) : "r"(__float_as_uint(a)), "r"(__float_as_uint(b)));
    return r;
}
__device__ __forceinline__ ull fma2(ull a, ull b, ull c) {
    ull d;
    asm("fma.rn.f32x2 %0, %1, %2, %3;" : "=l"(d) : "l"(a), "l"(b), "l"(c));
    return d;
}
__device__ __forceinline__ float2 upk(ull v) {
    unsigned lo, hi;
    asm("mov.b64 {%0, %1}, %2;" : "=r"(lo), "=r"(hi) : "l"(v));
    return make_float2(__uint_as_float(lo), __uint_as_float(hi));
}

// ---------------------------------------------------------------------------
// Projection GEMM: C = A[4096,1024] @ W^T + bias. SCATTER=true writes the
// result into [n][h][l][d] layout; false writes row-major (final output).
// BM=BN=128, BK=16, 256 threads, 8x8 micro via 32 FFMA2, reg prefetch.
// ---------------------------------------------------------------------------
template <bool SCATTER>
__device__ __forceinline__
void gemm_body(const float* __restrict__ A, const float* __restrict__ B,
               const float* __restrict__ bias, float* __restrict__ C,
               int bm, int bn)
{
    __shared__ float As[16 * 128];
    __shared__ float Bs[16 * 128];
    const int tid = threadIdx.x;
    const int ty = tid >> 4, tx = tid & 15;
    const int rr = tid >> 2, k4 = tid & 3;

    ull acc[8][4];
#pragma unroll
    for (int i = 0; i < 8; ++i)
#pragma unroll
        for (int j = 0; j < 4; ++j) acc[i][j] = 0ull;

    const float* Abase = A + (size_t)(bm * 128 + rr) * 1024 + k4 * 4;
    const float* Bbase = B + (size_t)(bn * 128 + rr) * 1024 + k4 * 4;

    float4 pa0 = *(const float4*)(Abase);
    float4 pa1 = *(const float4*)(Abase + (size_t)64 * 1024);
    float4 pb0 = *(const float4*)(Bbase);
    float4 pb1 = *(const float4*)(Bbase + (size_t)64 * 1024);

    for (int kt = 0; kt < 64; ++kt) {
        As[(k4 * 4 + 0) * 128 + rr] = pa0.x;
        As[(k4 * 4 + 1) * 128 + rr] = pa0.y;
        As[(k4 * 4 + 2) * 128 + rr] = pa0.z;
        As[(k4 * 4 + 3) * 128 + rr] = pa0.w;
        As[(k4 * 4 + 0) * 128 + rr + 64] = pa1.x;
        As[(k4 * 4 + 1) * 128 + rr + 64] = pa1.y;
        As[(k4 * 4 + 2) * 128 + rr + 64] = pa1.z;
        As[(k4 * 4 + 3) * 128 + rr + 64] = pa1.w;
        Bs[(k4 * 4 + 0) * 128 + rr] = pb0.x;
        Bs[(k4 * 4 + 1) * 128 + rr] = pb0.y;
        Bs[(k4 * 4 + 2) * 128 + rr] = pb0.z;
        Bs[(k4 * 4 + 3) * 128 + rr] = pb0.w;
        Bs[(k4 * 4 + 0) * 128 + rr + 64] = pb1.x;
        Bs[(k4 * 4 + 1) * 128 + rr + 64] = pb1.y;
        Bs[(k4 * 4 + 2) * 128 + rr + 64] = pb1.z;
        Bs[(k4 * 4 + 3) * 128 + rr + 64] = pb1.w;
        __syncthreads();

        if (kt < 63) {
            const int off = (kt + 1) * 16;
            pa0 = *(const float4*)(Abase + off);
            pa1 = *(const float4*)(Abase + (size_t)64 * 1024 + off);
            pb0 = *(const float4*)(Bbase + off);
            pb1 = *(const float4*)(Bbase + (size_t)64 * 1024 + off);
        }

#pragma unroll
        for (int k = 0; k < 16; ++k) {
            const float4 a0 = *(const float4*)(As + k * 128 + ty * 4);
            const float4 a1 = *(const float4*)(As + k * 128 + 64 + ty * 4);
            const ulonglong2 bpa = *(const ulonglong2*)(Bs + k * 128 + tx * 4);
            const ulonglong2 bpb = *(const ulonglong2*)(Bs + k * 128 + 64 + tx * 4);
            ull ad[8];
            ad[0] = pk2(a0.x, a0.x); ad[1] = pk2(a0.y, a0.y);
            ad[2] = pk2(a0.z, a0.z); ad[3] = pk2(a0.w, a0.w);
            ad[4] = pk2(a1.x, a1.x); ad[5] = pk2(a1.y, a1.y);
            ad[6] = pk2(a1.z, a1.z); ad[7] = pk2(a1.w, a1.w);
            const ull bp[4] = {bpa.x, bpa.y, bpb.x, bpb.y};
#pragma unroll
            for (int ii = 0; ii < 8; ++ii)
#pragma unroll
                for (int jj = 0; jj < 4; ++jj)
                    acc[ii][jj] = fma2(ad[ii], bp[jj], acc[ii][jj]);
        }
        __syncthreads();
    }
    // Epilogue with bias
#pragma unroll
    for (int jh = 0; jh < 2; ++jh) {
        const int col = bn * 128 + jh * 64 + tx * 4;
        const float4 bb = *(const float4*)(bias + col);
#pragma unroll
        for (int ii = 0; ii < 8; ++ii) {
            const int row = bm * 128 + ((ii < 4) ? (ty * 4 + ii) : (64 + ty * 4 + ii - 4));
            const float2 c01 = upk(acc[ii][jh * 2 + 0]);
            const float2 c23 = upk(acc[ii][jh * 2 + 1]);
            float4 o;
            o.x = c01.x + bb.x;
            o.y = c01.y + bb.y;
            o.z = c23.x + bb.z;
            o.w = c23.y + bb.w;
            if (SCATTER) {
                // row=(l,n), col=(h,d) -> [n][h][l][d]
                const int l = row >> 1, nn = row & 1;
                const int h = bn * 2 + jh, d = tx * 4;
                *(float4*)(C + ((size_t)(nn * 16 + h) * 2048 + l) * 64 + d) = o;
            } else {
                *(float4*)(C + (size_t)row * 1024 + col) = o;
            }
        }
    }
}

__global__ __launch_bounds__(256, 2)
void gemm_qkv_kernel(const float* __restrict__ q, const float* __restrict__ k,
                     const float* __restrict__ v,
                     const float* __restrict__ Wq, const float* __restrict__ bq,
                     const float* __restrict__ Wk, const float* __restrict__ bk,
                     const float* __restrict__ Wv, const float* __restrict__ bv,
                     float* __restrict__ Qp, float* __restrict__ Kp, float* __restrict__ Vp)
{
    const int which = blockIdx.z;
    const float* A    = (which == 0) ? q  : (which == 1) ? k  : v;
    const float* B    = (which == 0) ? Wq : (which == 1) ? Wk : Wv;
    const float* bias = (which == 0) ? bq : (which == 1) ? bk : bv;
    float*       C    = (which == 0) ? Qp : (which == 1) ? Kp : Vp;
    gemm_body<true>(A, B, bias, C, blockIdx.y, blockIdx.x);
}

__global__ __launch_bounds__(256, 2)
void gemm_o_kernel(const float* __restrict__ A, const float* __restrict__ B,
                   const float* __restrict__ bias, float* __restrict__ C)
{
    gemm_body<false>(A, B, bias, C, blockIdx.y, blockIdx.x);
}

// ---------------------------------------------------------------------------
// QK^T for one n: per-h GEMM  S[2048,2048] = Q[2048,64] @ K^T * 0.125
// BM=BN=128, BK=16 x4, 256 threads, same micro-tiling as gemm_body.
// ---------------------------------------------------------------------------
__global__ __launch_bounds__(256, 2)
void qk_kernel(int n)
{
    __shared__ float As[16 * 128];
    __shared__ float Bs[16 * 128];
    const int tid = threadIdx.x;
    const int h = blockIdx.z, bm = blockIdx.y, bn = blockIdx.x;
    const int nh = n * 16 + h;
    const int ty = tid >> 4, tx = tid & 15;
    const int rr = tid >> 2, k4 = tid & 3;

    const float* A = g_Qp + (size_t)nh * 131072;  // 2048*64
    const float* B = g_Kp + (size_t)nh * 131072;

    ull acc[8][4];
#pragma unroll
    for (int i = 0; i < 8; ++i)
#pragma unroll
        for (int j = 0; j < 4; ++j) acc[i][j] = 0ull;

    const float* Abase = A + (size_t)(bm * 128 + rr) * 64 + k4 * 4;
    const float* Bbase = B + (size_t)(bn * 128 + rr) * 64 + k4 * 4;

    float4 pa0 = *(const float4*)(Abase);
    float4 pa1 = *(const float4*)(Abase + 64 * 64);
    float4 pb0 = *(const float4*)(Bbase);
    float4 pb1 = *(const float4*)(Bbase + 64 * 64);

#pragma unroll
    for (int kt = 0; kt < 4; ++kt) {
        As[(k4 * 4 + 0) * 128 + rr] = pa0.x;
        As[(k4 * 4 + 1) * 128 + rr] = pa0.y;
        As[(k4 * 4 + 2) * 128 + rr] = pa0.z;
        As[(k4 * 4 + 3) * 128 + rr] = pa0.w;
        As[(k4 * 4 + 0) * 128 + rr + 64] = pa1.x;
        As[(k4 * 4 + 1) * 128 + rr + 64] = pa1.y;
        As[(k4 * 4 + 2) * 128 + rr + 64] = pa1.z;
        As[(k4 * 4 + 3) * 128 + rr + 64] = pa1.w;
        Bs[(k4 * 4 + 0) * 128 + rr] = pb0.x;
        Bs[(k4 * 4 + 1) * 128 + rr] = pb0.y;
        Bs[(k4 * 4 + 2) * 128 + rr] = pb0.z;
        Bs[(k4 * 4 + 3) * 128 + rr] = pb0.w;
        Bs[(k4 * 4 + 0) * 128 + rr + 64] = pb1.x;
        Bs[(k4 * 4 + 1) * 128 + rr + 64] = pb1.y;
        Bs[(k4 * 4 + 2) * 128 + rr + 64] = pb1.z;
        Bs[(k4 * 4 + 3) * 128 + rr + 64] = pb1.w;
        __syncthreads();

        if (kt < 3) {
            const int off = (kt + 1) * 16;
            pa0 = *(const float4*)(Abase + off);
            pa1 = *(const float4*)(Abase + 64 * 64 + off);
            pb0 = *(const float4*)(Bbase + off);
            pb1 = *(const float4*)(Bbase + 64 * 64 + off);
        }

#pragma unroll
        for (int k = 0; k < 16; ++k) {
            const float4 a0 = *(const float4*)(As + k * 128 + ty * 4);
            const float4 a1 = *(const float4*)(As + k * 128 + 64 + ty * 4);
            const ulonglong2 bpa = *(const ulonglong2*)(Bs + k * 128 + tx * 4);
            const ulonglong2 bpb = *(const ulonglong2*)(Bs + k * 128 + 64 + tx * 4);
            ull ad[8];
            ad[0] = pk2(a0.x, a0.x); ad[1] = pk2(a0.y, a0.y);
            ad[2] = pk2(a0.z, a0.z); ad[3] = pk2(a0.w, a0.w);
            ad[4] = pk2(a1.x, a1.x); ad[5] = pk2(a1.y, a1.y);
            ad[6] = pk2(a1.z, a1.z); ad[7] = pk2(a1.w, a1.w);
            const ull bp[4] = {bpa.x, bpa.y, bpb.x, bpb.y};
#pragma unroll
            for (int ii = 0; ii < 8; ++ii)
#pragma unroll
                for (int jj = 0; jj < 4; ++jj)
                    acc[ii][jj] = fma2(ad[ii], bp[jj], acc[ii][jj]);
        }
        __syncthreads();
    }
    // Epilogue: scale by 1/sqrt(64) and write scores
    float* Sbase = g_S + (size_t)h * 4194304;
#pragma unroll
    for (int jh = 0; jh < 2; ++jh) {
        const int col = bn * 128 + jh * 64 + tx * 4;
#pragma unroll
        for (int ii = 0; ii < 8; ++ii) {
            const int row = bm * 128 + ((ii < 4) ? (ty * 4 + ii) : (64 + ty * 4 + ii - 4));
            const float2 c01 = upk(acc[ii][jh * 2 + 0]);
            const float2 c23 = upk(acc[ii][jh * 2 + 1]);
            float4 o;
            o.x = c01.x * 0.125f;
            o.y = c01.y * 0.125f;
            o.z = c23.x * 0.125f;
            o.w = c23.y * 0.125f;
            *(float4*)(Sbase + (size_t)row * 2048 + col) = o;
        }
    }
}

// ---------------------------------------------------------------------------
// Select + softmax: one 256-thread block per score row (32768 blocks/pass).
// Row cached in registers. Pass b=3 uses warp-aggregated atomics (exponent
// byte -> heavy bin conflicts); passes b=2..0 use plain predicated atomics
// (few active keys, near-uniform bins) -- no match_any cost.
// ---------------------------------------------------------------------------
__global__ __launch_bounds__(256)
void sel_kernel()
{
    __shared__ unsigned hist[256];
    __shared__ unsigned s_pfx, s_T, s_km;
    __shared__ float    f_red[8];
    __shared__ unsigned u_red[8];
    __shared__ float    s_inv;

    const int tid = threadIdx.x, lane = tid & 31, wid = tid >> 5;
    float* srow = g_S + (size_t)blockIdx.x * 2048;

    float v[8];
    unsigned key[8];
    {
        const float4 f0 = *(const float4*)(srow + tid * 8);
        const float4 f1 = *(const float4*)(srow + tid * 8 + 4);
        v[0] = f0.x; v[1] = f0.y; v[2] = f0.z; v[3] = f0.w;
        v[4] = f1.x; v[5] = f1.y; v[6] = f1.z; v[7] = f1.w;
#pragma unroll
        for (int i = 0; i < 8; ++i) key[i] = f2key(v[i]);
    }

    // block max of keys
    {
        unsigned km = key[0];
#pragma unroll
        for (int i = 1; i < 8; ++i) km = (key[i] > km) ? key[i] : km;
#pragma unroll
        for (int o = 16; o > 0; o >>= 1) {
            const unsigned t = __shfl_xor_sync(0xffffffffu, km, o);
            km = (t > km) ? t : km;
        }
        if (lane == 0) u_red[wid] = km;
        __syncthreads();
        if (tid == 0) {
            unsigned m = u_red[0];
#pragma unroll
            for (int i = 1; i < 8; ++i) m = (u_red[i] > m) ? u_red[i] : m;
            s_km = m;
        }
    }

    unsigned prefix = 0, T = T_SEL;

    // ---- pass b=3: all 2048 keys; warp-aggregated (few distinct exp bins) ----
    {
        hist[tid] = 0;
        __syncthreads();
#pragma unroll
        for (int i = 0; i < 8; ++i) {
            const unsigned bin = key[i] >> 24;
            const unsigned grp = __match_any_sync(0xffffffffu, bin);
            if (lane == (__ffs(grp) - 1))
                atomicAdd(&hist[bin], (unsigned)__popc(grp));
        }
        __syncthreads();
        if (wid == 0) {
            unsigned c[8], lsum = 0;
#pragma unroll
            for (int i = 0; i < 8; ++i) { c[i] = hist[lane * 8 + i]; lsum += c[i]; }
            unsigned inc = lsum;
#pragma unroll
            for (int o = 1; o < 32; o <<= 1) {
                const unsigned t = __shfl_up_sync(0xffffffffu, inc, o);
                if (lane >= o) inc += t;
            }
            const unsigned exl = inc - lsum;
            if (T >= exl && T < exl + lsum) {
                unsigned cum = exl;
#pragma unroll
                for (int i = 0; i < 8; ++i) {
                    if (T < cum + c[i]) {
                        s_pfx = (unsigned)(lane * 8 + i) << 24;
                        s_T   = T - cum;
                        break;
                    }
                    cum += c[i];
                }
            }
        }
        __syncthreads();
        prefix = s_pfx;
        T = s_T;
        __syncthreads();
    }

    // ---- passes b=2..0: only prefix-matching keys; plain atomics ----
#pragma unroll
    for (int b = 2; b >= 0; --b) {
        hist[tid] = 0;
        __syncthreads();
        const unsigned himask = 0xFFFFFFFFu << ((b + 1) * 8);
#pragma unroll
        for (int i = 0; i < 8; ++i) {
            if ((key[i] & himask) == prefix)
                atomicAdd(&hist[(key[i] >> (b * 8)) & 255], 1u);
        }
        __syncthreads();
        if (wid == 0) {
            unsigned c[8], lsum = 0;
#pragma unroll
            for (int i = 0; i < 8; ++i) { c[i] = hist[lane * 8 + i]; lsum += c[i]; }
            unsigned inc = lsum;
#pragma unroll
            for (int o = 1; o < 32; o <<= 1) {
                const unsigned t = __shfl_up_sync(0xffffffffu, inc, o);
                if (lane >= o) inc += t;
            }
            const unsigned exl = inc - lsum;
            if (T >= exl && T < exl + lsum) {
                unsigned cum = exl;
#pragma unroll
                for (int i = 0; i < 8; ++i) {
                    if (T < cum + c[i]) {
                        s_pfx = prefix | ((unsigned)(lane * 8 + i) << (b * 8));
                        s_T   = T - cum;
                        break;
                    }
                    cum += c[i];
                }
            }
        }
        __syncthreads();
        prefix = s_pfx;
        T = s_T;
        __syncthreads();
    }

    // masked exp + block sum
    const unsigned tk = prefix;
    const float m = key2f(s_km);
    float w[8];
    float lsum = 0.0f;
#pragma unroll
    for (int i = 0; i < 8; ++i) {
        w[i] = (key[i] >= tk) ? fexp(v[i] - m) : 0.0f;
        lsum += w[i];
    }
#pragma unroll
    for (int o = 16; o > 0; o >>= 1)
        lsum += __shfl_xor_sync(0xffffffffu, lsum, o);
    if (lane == 0) f_red[wid] = lsum;
    __syncthreads();
    if (tid == 0) {
        float t = 0.0f;
#pragma unroll
        for (int i = 0; i < 8; ++i) t += f_red[i];
        s_inv = 1.0f / t;
    }
    __syncthreads();
    const float inv = s_inv;

    float4 o0 = make_float4(w[0] * inv, w[1] * inv, w[2] * inv, w[3] * inv);
    float4 o1 = make_float4(w[4] * inv, w[5] * inv, w[6] * inv, w[7] * inv);
    *(float4*)(srow + tid * 8)     = o0;
    *(float4*)(srow + tid * 8 + 4) = o1;
}

// ---------------------------------------------------------------------------
// PV for one n: per-h GEMM  O[2048,64] = W[2048,2048] @ V[2048,64]
// BM=64, BN=64 (full d), BK=128, 256 threads, 4l x 4d micro via FFMA2
// (the R13-measured-good micro-loop: W l-pairs packed, V dup'd).
// Wt transposed (stride 65); W reads warp-broadcast. 3 blocks/SM; grid 32x16.
// Output scattered to g_O[(l,n)][d*16+h] for the O projection.
// ---------------------------------------------------------------------------
#define PV_LSTR 65
#define PV_SMEM_BYTES ((128 * PV_LSTR + 128 * 64) * 4)

__global__ __launch_bounds__(256, 3)
void pv_kernel(int n)
{
    extern __shared__ float psm[];
    float* Wt = psm;                 // [128 s][PV_LSTR l] (transposed)
    float* Vs = psm + 128 * PV_LSTR; // [128 s][64 d]

    const int tid = threadIdx.x;
    const int h = blockIdx.y, bm = blockIdx.x;
    const int nh = n * 16 + h;
    const int ty = tid >> 4, tx = tid & 15;   // ty: l quad (0..15), tx: d quad

    const float* Wrow  = g_S + (size_t)h * 4194304 + (size_t)bm * 64 * 2048;
    const float* Vbase = g_Vp + (size_t)nh * 131072;

    ull acc[2][4];
#pragma unroll
    for (int i = 0; i < 2; ++i)
#pragma unroll
        for (int j = 0; j < 4; ++j) acc[i][j] = 0ull;

    for (int kt = 0; kt < 16; ++kt) {
        // W tile [64 l][128 s] -> transposed Wt[s][l]
#pragma unroll
        for (int i = 0; i < 8; ++i) {
            const int idx = i * 256 + tid;
            const int lr = idx >> 5, sq = idx & 31;
            const float4 w = *(const float4*)(Wrow + (size_t)lr * 2048 + kt * 128 + sq * 4);
            Wt[(sq * 4 + 0) * PV_LSTR + lr] = w.x;
            Wt[(sq * 4 + 1) * PV_LSTR + lr] = w.y;
            Wt[(sq * 4 + 2) * PV_LSTR + lr] = w.z;
            Wt[(sq * 4 + 3) * PV_LSTR + lr] = w.w;
        }
        // V tile [128 s][64 d]
#pragma unroll
        for (int i = 0; i < 8; ++i) {
            const int idx = i * 256 + tid;
            const int sr = idx >> 4, d4 = idx & 15;
            *(float4*)(Vs + sr * 64 + d4 * 4) =
                *(const float4*)(Vbase + (size_t)(kt * 128 + sr) * 64 + d4 * 4);
        }
        __syncthreads();

        const float* wb = Wt + ty * 4;
        const float* vb = Vs + tx * 4;
#pragma unroll 4
        for (int s = 0; s < 128; ++s) {
            const float* wr = wb + s * PV_LSTR;   // W[l = ty*4 .. ty*4+3][s]
            const ull p0 = pk2(wr[0], wr[1]);
            const ull p1 = pk2(wr[2], wr[3]);
            const float4 vv = *(const float4*)(vb + s * 64);
            const ull v0 = pk2(vv.x, vv.x);
            const ull v1 = pk2(vv.y, vv.y);
            const ull v2 = pk2(vv.z, vv.z);
            const ull v3 = pk2(vv.w, vv.w);
            acc[0][0] = fma2(p0, v0, acc[0][0]);
            acc[0][1] = fma2(p0, v1, acc[0][1]);
            acc[0][2] = fma2(p0, v2, acc[0][2]);
            acc[0][3] = fma2(p0, v3, acc[0][3]);
            acc[1][0] = fma2(p1, v0, acc[1][0]);
            acc[1][1] = fma2(p1, v1, acc[1][1]);
            acc[1][2] = fma2(p1, v2, acc[1][2]);
            acc[1][3] = fma2(p1, v3, acc[1][3]);
        }
        __syncthreads();
    }

    // Epilogue: scatter to g_O[(l,n)][d*16+h]
#pragma unroll
    for (int lp = 0; lp < 2; ++lp) {
        const int l0 = bm * 64 + ty * 4 + lp * 2;
        float* o0 = g_O + (size_t)(l0 * 2 + n) * 1024 + h;
        float* o1 = g_O + (size_t)((l0 + 1) * 2 + n) * 1024 + h;
#pragma unroll
        for (int j = 0; j < 4; ++j) {
            const float2 r = upk(acc[lp][j]);
            const int d = tx * 4 + j;
            o0[d * 16] = r.x;
            o1[d * 16] = r.y;
        }
    }
}

// ---------------------------------------------------------------------------
// Launch
// ---------------------------------------------------------------------------
extern "C" void kernel_launch(void* const* d_in, const int* in_sizes, int n_in,
                              void* d_out, int out_size)
{
    (void)in_sizes; (void)n_in; (void)out_size;
    const float* query = (const float*)d_in[0];
    const float* key   = (const float*)d_in[1];
    const float* value = (const float*)d_in[2];
    const float* Wq = (const float*)d_in[3];
    const float* bq = (const float*)d_in[4];
    const float* Wk = (const float*)d_in[5];
    const float* bk = (const float*)d_in[6];
    const float* Wv = (const float*)d_in[7];
    const float* bv = (const float*)d_in[8];
    const float* Wo = (const float*)d_in[9];
    const float* bo = (const float*)d_in[10];

    float *Qp, *Kp, *Vp, *O;
    cudaGetSymbolAddress((void**)&Qp, g_Qp);
    cudaGetSymbolAddress((void**)&Kp, g_Kp);
    cudaGetSymbolAddress((void**)&Vp, g_Vp);
    cudaGetSymbolAddress((void**)&O,  g_O);

    cudaFuncSetAttribute(pv_kernel, cudaFuncAttributeMaxDynamicSharedMemorySize,
                         PV_SMEM_BYTES);

    gemm_qkv_kernel<<<dim3(8, 32, 3), 256>>>(query, key, value,
                                             Wq, bq, Wk, bk, Wv, bv,
                                             Qp, Kp, Vp);

    for (int n = 0; n < N_B; ++n) {
        qk_kernel<<<dim3(16, 16, 16), 256>>>(n);
        sel_kernel<<<32768, 256>>>();
        pv_kernel<<<dim3(32, 16), 256, PV_SMEM_BYTES>>>(n);
    }

    gemm_o_kernel<<<dim3(8, 32), 256>>>(O, Wo, bo, (float*)d_out);
}